// round 10
// baseline (speedup 1.0000x reference)
#include <cuda_runtime.h>
#include <cuda_bf16.h>
#include <math.h>
#include <stdint.h>

#define BB   16
#define NN   512
#define DD   512
#define HH   8
#define KTOP 16
#define HD   64
#define MSL  512
#define ROWS (BB*NN)     // 8192
#define DFF  2048

// ---------------- scratch (static device memory; no allocs allowed) ----------
__device__ float g_v    [ROWS*DD];
__device__ float g_x1   [ROWS*DD];

__device__ __nv_bfloat16 g_qb_h  [ROWS*DD];
__device__ __nv_bfloat16 g_qb_l  [ROWS*DD];
__device__ __nv_bfloat16 g_kb_h  [ROWS*DD];
__device__ __nv_bfloat16 g_kb_l  [ROWS*DD];
__device__ __nv_bfloat16 g_xnb_h  [ROWS*DD];
__device__ __nv_bfloat16 g_xnb_l  [ROWS*DD];
__device__ __nv_bfloat16 g_xn2b_h [ROWS*DD];
__device__ __nv_bfloat16 g_xn2b_l [ROWS*DD];
__device__ __nv_bfloat16 g_attnb_h[ROWS*DD];
__device__ __nv_bfloat16 g_attnb_l[ROWS*DD];
__device__ __nv_bfloat16 g_ffb_h  [(size_t)ROWS*DFF];
__device__ __nv_bfloat16 g_ffb_l  [(size_t)ROWS*DFF];
__device__ __nv_bfloat16 g_wqkv_h [3*DD*DD];      // packed Q|K|V, [1536][512]
__device__ __nv_bfloat16 g_wqkv_l [3*DD*DD];
__device__ __nv_bfloat16 g_wto_h  [DD*DD];
__device__ __nv_bfloat16 g_wto_l  [DD*DD];
__device__ __nv_bfloat16 g_wt1_h  [(size_t)DD*DFF];
__device__ __nv_bfloat16 g_wt1_l  [(size_t)DD*DFF];
__device__ __nv_bfloat16 g_wt2_h  [(size_t)DFF*DD];
__device__ __nv_bfloat16 g_wt2_l  [(size_t)DFF*DD];

// ================= PTX helpers (base sm_103 target legal) ====================
__device__ __forceinline__ uint32_t smem_u32(const void* p) {
    uint32_t a;
    asm("{ .reg .u64 t; cvta.to.shared.u64 t, %1; cvt.u32.u64 %0, t; }" : "=r"(a) : "l"(p));
    return a;
}
__device__ __forceinline__ void cpa16(uint32_t dst, const void* src) {
    asm volatile("cp.async.cg.shared.global [%0], [%1], 16;" :: "r"(dst), "l"(src));
}
__device__ __forceinline__ void cpa_commit() {
    asm volatile("cp.async.commit_group;" ::: "memory");
}
template<int N>
__device__ __forceinline__ void cpa_wait() {
    asm volatile("cp.async.wait_group %0;" :: "n"(N) : "memory");
}
__device__ __forceinline__ void ldsm4(uint32_t* r, uint32_t addr) {
    asm volatile("ldmatrix.sync.aligned.m8n8.x4.shared.b16 {%0,%1,%2,%3}, [%4];"
                 : "=r"(r[0]), "=r"(r[1]), "=r"(r[2]), "=r"(r[3]) : "r"(addr));
}
__device__ __forceinline__ void mma16816(float* c, const uint32_t* a, const uint32_t* b) {
    asm volatile(
        "mma.sync.aligned.m16n8k16.row.col.f32.bf16.bf16.f32 "
        "{%0,%1,%2,%3}, {%4,%5,%6,%7}, {%8,%9}, {%0,%1,%2,%3};"
        : "+f"(c[0]), "+f"(c[1]), "+f"(c[2]), "+f"(c[3])
        : "r"(a[0]), "r"(a[1]), "r"(a[2]), "r"(a[3]), "r"(b[0]), "r"(b[1]));
}

#define LDA 40                         // padded smem row (elements)
#define TILEB (128 * LDA * 2)          // 10240 bytes per tile
#define BUFB  (4 * TILEB)              // Ah,Al,Bh,Bl per buffer

// ======= shared mainloop: bf16x3 triple-mma over K, double-buffered =========
#define GEMM_CORE(APH, APL, BPH, BPL, STRIDE, SCOUNT)                          \
    int r0 = tid >> 2, c0 = (tid & 3) * 8;                                     \
    int r1 = r0 + 64;                                                          \
    uint32_t off0 = (uint32_t)(r0 * LDA + c0) * 2;                             \
    uint32_t off1 = (uint32_t)(r1 * LDA + c0) * 2;                             \
    auto load_stage = [&](int s, int buf) {                                    \
        int k0 = s * 32;                                                       \
        uint32_t b = sbase + buf * BUFB;                                       \
        cpa16(b             + off0, APH + (size_t)r0 * STRIDE + k0 + c0);      \
        cpa16(b             + off1, APH + (size_t)r1 * STRIDE + k0 + c0);      \
        cpa16(b + TILEB     + off0, APL + (size_t)r0 * STRIDE + k0 + c0);      \
        cpa16(b + TILEB     + off1, APL + (size_t)r1 * STRIDE + k0 + c0);      \
        cpa16(b + 2 * TILEB + off0, BPH + (size_t)r0 * STRIDE + k0 + c0);      \
        cpa16(b + 2 * TILEB + off1, BPH + (size_t)r1 * STRIDE + k0 + c0);      \
        cpa16(b + 3 * TILEB + off0, BPL + (size_t)r0 * STRIDE + k0 + c0);      \
        cpa16(b + 3 * TILEB + off1, BPL + (size_t)r1 * STRIDE + k0 + c0);      \
    };                                                                         \
    load_stage(0, 0);                                                          \
    cpa_commit();                                                              \
    uint32_t a_off[2], b_off[4];                                               \
    _Pragma("unroll")                                                          \
    for (int mt = 0; mt < 2; mt++) {                                           \
        int row = wr * 32 + mt * 16 + (lane & 15);                             \
        a_off[mt] = (uint32_t)(row * LDA + (lane >> 4) * 8) * 2;               \
    }                                                                          \
    _Pragma("unroll")                                                          \
    for (int nt = 0; nt < 4; nt++) {                                           \
        int nrow = wc * 64 + nt * 16 + (lane & 7) + ((lane >> 4) & 1) * 8;     \
        b_off[nt] = (uint32_t)(nrow * LDA + ((lane >> 3) & 1) * 8) * 2;        \
    }                                                                          \
    for (int s = 0; s < SCOUNT; s++) {                                         \
        int buf = s & 1;                                                       \
        if (s + 1 < SCOUNT) { load_stage(s + 1, buf ^ 1); cpa_commit(); cpa_wait<1>(); } \
        else               { cpa_wait<0>(); }                                  \
        __syncthreads();                                                       \
        uint32_t ah = sbase + buf * BUFB;                                      \
        uint32_t al = ah + TILEB;                                              \
        uint32_t bh = ah + 2 * TILEB;                                          \
        uint32_t bl = ah + 3 * TILEB;                                          \
        _Pragma("unroll")                                                      \
        for (int kk = 0; kk < 2; kk++) {                                       \
            uint32_t afh[2][4], afl[2][4];                                     \
            _Pragma("unroll")                                                  \
            for (int mt = 0; mt < 2; mt++) {                                   \
                ldsm4(afh[mt], ah + a_off[mt] + kk * 32);                      \
                ldsm4(afl[mt], al + a_off[mt] + kk * 32);                      \
            }                                                                  \
            _Pragma("unroll")                                                  \
            for (int nt = 0; nt < 4; nt++) {                                   \
                uint32_t bfh[4], bfl[4];                                       \
                ldsm4(bfh, bh + b_off[nt] + kk * 32);                          \
                ldsm4(bfl, bl + b_off[nt] + kk * 32);                          \
                _Pragma("unroll")                                              \
                for (int mt = 0; mt < 2; mt++) {                               \
                    mma16816(acc[mt][nt * 2 + 0], afh[mt], bfh + 0);           \
                    mma16816(acc[mt][nt * 2 + 1], afh[mt], bfh + 2);           \
                    mma16816(acc[mt][nt * 2 + 0], afl[mt], bfh + 0);           \
                    mma16816(acc[mt][nt * 2 + 1], afl[mt], bfh + 2);           \
                    mma16816(acc[mt][nt * 2 + 0], afh[mt], bfl + 0);           \
                    mma16816(acc[mt][nt * 2 + 1], afh[mt], bfl + 2);           \
                }                                                              \
            }                                                                  \
        }                                                                      \
        __syncthreads();                                                       \
    }

#define ACC_INIT                                                               \
    float acc[2][8][4];                                                        \
    _Pragma("unroll")                                                          \
    for (int i = 0; i < 2; i++)                                                \
        _Pragma("unroll")                                                      \
        for (int j = 0; j < 8; j++)                                            \
            _Pragma("unroll")                                                  \
            for (int q = 0; q < 4; q++) acc[i][j][q] = 0.f;

// ================= generic GEMM, 128x128 tile ===============================
// MODE 1: C(fp32) = acc + bias + res
// MODE 2: hi/lo bf16 = gelu(acc + bias)
template<int MODE>
__global__ void __launch_bounds__(256, 2) gemm_mma(
    const __nv_bfloat16* __restrict__ Ah, const __nv_bfloat16* __restrict__ Al,
    const __nv_bfloat16* __restrict__ Bh, const __nv_bfloat16* __restrict__ Bl,
    const float* __restrict__ bias, const float* __restrict__ res,
    void* __restrict__ Cout, void* __restrict__ Cout2, int M, int N, int Kd)
{
    extern __shared__ char smem[];
    uint32_t sbase = smem_u32(smem);
    int tid = threadIdx.x, wid = tid >> 5, lane = tid & 31;
    int n0 = blockIdx.x * 128, m0 = blockIdx.y * 128;
    int wr = wid & 3, wc = wid >> 2;

    const __nv_bfloat16* Aph = Ah + (size_t)m0 * Kd;
    const __nv_bfloat16* Apl = Al + (size_t)m0 * Kd;
    const __nv_bfloat16* Bph = Bh + (size_t)n0 * Kd;
    const __nv_bfloat16* Bpl = Bl + (size_t)n0 * Kd;

    ACC_INIT;
    int S = Kd >> 5;
    GEMM_CORE(Aph, Apl, Bph, Bpl, Kd, S);

    int gr = lane >> 2, tg = lane & 3;
    #pragma unroll
    for (int mt = 0; mt < 2; mt++) {
        int rbase = m0 + wr * 32 + mt * 16 + gr;
        #pragma unroll
        for (int j = 0; j < 8; j++) {
            int col = n0 + wc * 64 + j * 8 + tg * 2;
            #pragma unroll
            for (int half = 0; half < 2; half++) {
                int row = rbase + half * 8;
                float v0 = acc[mt][j][half * 2 + 0] + bias[col];
                float v1 = acc[mt][j][half * 2 + 1] + bias[col + 1];
                if (MODE == 2) {
                    v0 = 0.5f * v0 * (1.0f + erff(v0 * 0.70710678118654752f));
                    v1 = 0.5f * v1 * (1.0f + erff(v1 * 0.70710678118654752f));
                    __nv_bfloat162 ph, pl;
                    ph.x = __float2bfloat16(v0);
                    ph.y = __float2bfloat16(v1);
                    pl.x = __float2bfloat16(v0 - __bfloat162float(ph.x));
                    pl.y = __float2bfloat16(v1 - __bfloat162float(ph.y));
                    *(__nv_bfloat162*)((__nv_bfloat16*)Cout  + (size_t)row * N + col) = ph;
                    *(__nv_bfloat162*)((__nv_bfloat16*)Cout2 + (size_t)row * N + col) = pl;
                } else {
                    const float* rr = res + (size_t)row * N + col;
                    float2 o; o.x = v0 + rr[0]; o.y = v1 + rr[1];
                    *(float2*)((float*)Cout + (size_t)row * N + col) = o;
                }
            }
        }
    }
}

// ================= fused QKV GEMM: N=1536 packed, mixed epilogue ============
__global__ void __launch_bounds__(256, 2) gemm_qkv(
    const __nv_bfloat16* __restrict__ Ah, const __nv_bfloat16* __restrict__ Al,
    const __nv_bfloat16* __restrict__ Bh, const __nv_bfloat16* __restrict__ Bl,
    const float* __restrict__ bq, const float* __restrict__ bk,
    const float* __restrict__ bv,
    __nv_bfloat16* __restrict__ qh, __nv_bfloat16* __restrict__ ql,
    __nv_bfloat16* __restrict__ kh, __nv_bfloat16* __restrict__ kl,
    float* __restrict__ v)
{
    extern __shared__ char smem[];
    uint32_t sbase = smem_u32(smem);
    int tid = threadIdx.x, wid = tid >> 5, lane = tid & 31;
    int n0 = blockIdx.x * 128, m0 = blockIdx.y * 128;
    int wr = wid & 3, wc = wid >> 2;

    const __nv_bfloat16* Aph = Ah + (size_t)m0 * DD;
    const __nv_bfloat16* Apl = Al + (size_t)m0 * DD;
    const __nv_bfloat16* Bph = Bh + (size_t)n0 * DD;
    const __nv_bfloat16* Bpl = Bl + (size_t)n0 * DD;

    ACC_INIT;
    GEMM_CORE(Aph, Apl, Bph, Bpl, DD, 16);

    int gr = lane >> 2, tg = lane & 3;
    int sel = n0 >> 9;                       // 0=Q, 1=K, 2=V
    const float* bias = (sel == 0) ? bq : (sel == 1) ? bk : bv;
    __nv_bfloat16* oh = (sel == 0) ? qh : kh;
    __nv_bfloat16* ol = (sel == 0) ? ql : kl;
    int nloc = n0 & 511;
    #pragma unroll
    for (int mt = 0; mt < 2; mt++) {
        int rbase = m0 + wr * 32 + mt * 16 + gr;
        #pragma unroll
        for (int j = 0; j < 8; j++) {
            int col = nloc + wc * 64 + j * 8 + tg * 2;
            #pragma unroll
            for (int half = 0; half < 2; half++) {
                int row = rbase + half * 8;
                float v0 = acc[mt][j][half * 2 + 0] + bias[col];
                float v1 = acc[mt][j][half * 2 + 1] + bias[col + 1];
                if (sel == 2) {
                    float2 o; o.x = v0; o.y = v1;
                    *(float2*)(v + (size_t)row * DD + col) = o;
                } else {
                    __nv_bfloat162 ph, pl;
                    ph.x = __float2bfloat16(v0);
                    ph.y = __float2bfloat16(v1);
                    pl.x = __float2bfloat16(v0 - __bfloat162float(ph.x));
                    pl.y = __float2bfloat16(v1 - __bfloat162float(ph.y));
                    *(__nv_bfloat162*)(oh + (size_t)row * DD + col) = ph;
                    *(__nv_bfloat162*)(ol + (size_t)row * DD + col) = pl;
                }
            }
        }
    }
}

// ===== fused attention: logits (bf16x3 HMMA) + top-16 + softmax + A*V =======
// One CTA = one (b,h) x 32-query block. K streamed in 4 chunks of 128.
// smem: A tiles (2 kstages x hi/lo, 32xLDA)   @ 0      (4 x 2560  = 10240 B)
//       B tiles (2 kstages x hi/lo, 128xLDA)  @ 10240  (4 x 10240 = 40960 B)
//       slog    (32 x 128 fp32)               @ 51200  (16384 B)
#define FA_A    0
#define FA_B    10240
#define FA_LOG  51200
#define FA_SMEM 67584
#define ATILE   (32 * LDA * 2)   // 2560

__global__ void __launch_bounds__(256) attn_fused(
    const __nv_bfloat16* __restrict__ Qh, const __nv_bfloat16* __restrict__ Ql,
    const __nv_bfloat16* __restrict__ Kh, const __nv_bfloat16* __restrict__ Kl,
    const float* __restrict__ rel, const float* __restrict__ v,
    __nv_bfloat16* __restrict__ ah, __nv_bfloat16* __restrict__ al)
{
    extern __shared__ char smem[];
    uint32_t sbase = smem_u32(smem);
    float* slog = (float*)(smem + FA_LOG);

    int tid = threadIdx.x, wid = tid >> 5, lane = tid & 31;
    int n0 = blockIdx.x * 32;
    int bh = blockIdx.y;
    int b = bh >> 3, h = bh & 7;

    const __nv_bfloat16* Aph = Qh + ((size_t)(b * NN + n0)) * DD + h * HD;
    const __nv_bfloat16* Apl = Ql + ((size_t)(b * NN + n0)) * DD + h * HD;
    const __nv_bfloat16* Bph = Kh + ((size_t)b * NN) * DD + h * HD;
    const __nv_bfloat16* Bpl = Kl + ((size_t)b * NN) * DD + h * HD;

    // ---- prologue: load A (32x64 hi/lo, both k-stages) + B chunk 0 ----------
    if (tid < 128) {
        int r = tid >> 2, c = (tid & 3) * 8;       // r 0..31, c 0,8,16,24
        uint32_t o = (uint32_t)(r * LDA + c) * 2;
        #pragma unroll
        for (int s = 0; s < 2; s++) {
            cpa16(sbase + FA_A + (s * 2 + 0) * ATILE + o, Aph + (size_t)r * DD + s * 32 + c);
            cpa16(sbase + FA_A + (s * 2 + 1) * ATILE + o, Apl + (size_t)r * DD + s * 32 + c);
        }
    }
    int br0 = tid >> 1, bc0 = (tid & 1) * 16;      // 128 rows x 2 halves of 32B... use 2-chunk scheme
    // B loader: per tile (stage,hl): 128 rows x 4 x cpa16; thread does 2.
    int r0 = tid >> 2, c0 = (tid & 3) * 8;
    int r1 = r0 + 64;
    uint32_t bo0 = (uint32_t)(r0 * LDA + c0) * 2;
    uint32_t bo1 = (uint32_t)(r1 * LDA + c0) * 2;
    auto load_chunk = [&](int ch) {
        const __nv_bfloat16* kh2 = Bph + (size_t)ch * 128 * DD;
        const __nv_bfloat16* kl2 = Bpl + (size_t)ch * 128 * DD;
        #pragma unroll
        for (int s = 0; s < 2; s++) {
            uint32_t th = sbase + FA_B + (s * 2 + 0) * TILEB;
            uint32_t tl = sbase + FA_B + (s * 2 + 1) * TILEB;
            cpa16(th + bo0, kh2 + (size_t)r0 * DD + s * 32 + c0);
            cpa16(th + bo1, kh2 + (size_t)r1 * DD + s * 32 + c0);
            cpa16(tl + bo0, kl2 + (size_t)r0 * DD + s * 32 + c0);
            cpa16(tl + bo1, kl2 + (size_t)r1 * DD + s * 32 + c0);
        }
    };
    load_chunk(0);
    cpa_commit();

    // fragment addresses
    uint32_t a_off[2];
    #pragma unroll
    for (int mt = 0; mt < 2; mt++) {
        int row = mt * 16 + (lane & 15);
        a_off[mt] = (uint32_t)(row * LDA + (lane >> 4) * 8) * 2;
    }
    int nrow = wid * 16 + (lane & 7) + ((lane >> 4) & 1) * 8;
    uint32_t b_off = (uint32_t)(nrow * LDA + ((lane >> 3) & 1) * 8) * 2;

    int gr = lane >> 2, tg = lane & 3;
    float vals[4][16];

    for (int ch = 0; ch < 4; ch++) {
        cpa_wait<0>();
        __syncthreads();

        float acc[2][2][4];
        #pragma unroll
        for (int i = 0; i < 2; i++)
            #pragma unroll
            for (int j = 0; j < 2; j++)
                #pragma unroll
                for (int q = 0; q < 4; q++) acc[i][j][q] = 0.f;

        #pragma unroll
        for (int s = 0; s < 2; s++) {
            uint32_t aTh = sbase + FA_A + (s * 2 + 0) * ATILE;
            uint32_t aTl = sbase + FA_A + (s * 2 + 1) * ATILE;
            uint32_t bTh = sbase + FA_B + (s * 2 + 0) * TILEB;
            uint32_t bTl = sbase + FA_B + (s * 2 + 1) * TILEB;
            #pragma unroll
            for (int kk = 0; kk < 2; kk++) {
                uint32_t afh[2][4], afl[2][4], bfh[4], bfl[4];
                #pragma unroll
                for (int mt = 0; mt < 2; mt++) {
                    ldsm4(afh[mt], aTh + a_off[mt] + kk * 32);
                    ldsm4(afl[mt], aTl + a_off[mt] + kk * 32);
                }
                ldsm4(bfh, bTh + b_off + kk * 32);
                ldsm4(bfl, bTl + b_off + kk * 32);
                #pragma unroll
                for (int mt = 0; mt < 2; mt++) {
                    mma16816(acc[mt][0], afh[mt], bfh + 0);
                    mma16816(acc[mt][1], afh[mt], bfh + 2);
                    mma16816(acc[mt][0], afl[mt], bfh + 0);
                    mma16816(acc[mt][1], afl[mt], bfh + 2);
                    mma16816(acc[mt][0], afh[mt], bfl + 0);
                    mma16816(acc[mt][1], afh[mt], bfl + 2);
                }
            }
        }
        __syncthreads();               // B smem reads done -> safe to prefetch

        if (ch < 3) { load_chunk(ch + 1); cpa_commit(); }

        // dump acc -> slog with scale + rel bias
        #pragma unroll
        for (int mt = 0; mt < 2; mt++) {
            #pragma unroll
            for (int jj = 0; jj < 2; jj++) {
                int cb = wid * 16 + jj * 8 + tg * 2;
                int mg = ch * 128 + cb;
                #pragma unroll
                for (int half = 0; half < 2; half++) {
                    int rloc = mt * 16 + gr + half * 8;
                    int ng = n0 + rloc;
                    slog[rloc * 128 + cb]     = acc[mt][jj][half * 2 + 0] * 0.125f + rel[(mg + 0 - ng + MSL - 1) * HH + h];
                    slog[rloc * 128 + cb + 1] = acc[mt][jj][half * 2 + 1] * 0.125f + rel[(mg + 1 - ng + MSL - 1) * HH + h];
                }
            }
        }
        __syncthreads();               // slog visible

        // collect candidates: warp w -> rows w*4..w*4+3; m = 32*t + lane
        #pragma unroll
        for (int rr = 0; rr < 4; rr++) {
            int rloc = wid * 4 + rr;
            #pragma unroll
            for (int q2 = 0; q2 < 4; q2++)
                vals[rr][ch * 4 + q2] = slog[rloc * 128 + q2 * 32 + lane];
        }
        __syncthreads();               // readers done before next chunk's dump
    }

    // ---- per-row top-16 + softmax + sparse A*V (identical to topk_kernel) ---
    const float* vbase = v + ((size_t)b * NN) * DD + h * HD;
    #pragma unroll
    for (int rr = 0; rr < 4; rr++) {
        int n = n0 + wid * 4 + rr;

        unsigned mask = 0xFFFFu;
        float selv = 0.f;
        int   selm = 0;
        #pragma unroll
        for (int r = 0; r < 16; r++) {
            float bv = -INFINITY; int bs = 0;
            #pragma unroll
            for (int t = 0; t < 16; t++) {
                bool live = (mask >> t) & 1u;
                if (live && vals[rr][t] > bv) { bv = vals[rr][t]; bs = t; }
            }
            float rv = bv;
            int rm = bs * 32 + lane;
            #pragma unroll
            for (int off = 16; off; off >>= 1) {
                float ov = __shfl_xor_sync(0xFFFFFFFFu, rv, off);
                int   om = __shfl_xor_sync(0xFFFFFFFFu, rm, off);
                if (ov > rv || (ov == rv && om < rm)) { rv = ov; rm = om; }
            }
            if ((rm & 31) == lane) mask &= ~(1u << (rm >> 5));
            if (lane == r) { selv = rv; selm = rm; }
        }

        float maxv = __shfl_sync(0xFFFFFFFFu, selv, 0);
        float e = (lane < 16) ? expf(selv - maxv) : 0.f;
        float s = e;
        #pragma unroll
        for (int off = 16; off; off >>= 1) s += __shfl_xor_sync(0xFFFFFFFFu, s, off);
        float p = e / s;

        float o0 = 0.f, o1 = 0.f;
        #pragma unroll
        for (int l = 0; l < 16; l++) {
            float pl = __shfl_sync(0xFFFFFFFFu, p, l);
            int   ml = __shfl_sync(0xFFFFFFFFu, selm, l);
            const float* vr = vbase + (size_t)ml * DD;
            o0 += pl * vr[lane];
            o1 += pl * vr[lane + 32];
        }
        size_t base = ((size_t)(b * NN + n)) * DD + h * HD;
        __nv_bfloat16 h0 = __float2bfloat16(o0);
        __nv_bfloat16 h1 = __float2bfloat16(o1);
        ah[base + lane]      = h0;
        ah[base + lane + 32] = h1;
        al[base + lane]      = __float2bfloat16(o0 - __bfloat162float(h0));
        al[base + lane + 32] = __float2bfloat16(o1 - __bfloat162float(h1));
    }
    (void)br0; (void)bc0;
}

// ---------------- weight transpose + fp32 -> bf16 hi/lo ---------------------
__global__ void __launch_bounds__(256) wconv(
    const float* __restrict__ w, __nv_bfloat16* __restrict__ wth,
    __nv_bfloat16* __restrict__ wtl, int Kd, int Nd)
{
    __shared__ float t[32][33];
    int k0 = blockIdx.x * 32, n0 = blockIdx.y * 32;
    int tx = threadIdx.x & 31, ty = threadIdx.x >> 5;
    #pragma unroll
    for (int i = 0; i < 4; i++)
        t[ty + 8 * i][tx] = w[(size_t)(k0 + ty + 8 * i) * Nd + n0 + tx];
    __syncthreads();
    #pragma unroll
    for (int i = 0; i < 4; i++) {
        float v = t[tx][ty + 8 * i];
        __nv_bfloat16 h = __float2bfloat16(v);
        size_t o = (size_t)(n0 + ty + 8 * i) * Kd + k0 + tx;
        wth[o] = h;
        wtl[o] = __float2bfloat16(v - __bfloat162float(h));
    }
}

// ---------------- LayerNorm -> bf16 hi/lo ------------------------------------
__global__ void __launch_bounds__(256) ln_kernel(
    const float* __restrict__ x, const float* __restrict__ g,
    const float* __restrict__ be, __nv_bfloat16* __restrict__ oh,
    __nv_bfloat16* __restrict__ ol)
{
    int row = blockIdx.x;
    const float* xr = x + (size_t)row * DD;
    int t = threadIdx.x;
    float v0 = xr[t], v1 = xr[t + 256];
    float s = v0 + v1, ss = v0 * v0 + v1 * v1;
    #pragma unroll
    for (int o = 16; o; o >>= 1) {
        s  += __shfl_xor_sync(0xFFFFFFFFu, s,  o);
        ss += __shfl_xor_sync(0xFFFFFFFFu, ss, o);
    }
    __shared__ float red0[8], red1[8];
    __shared__ float smean, srstd;
    int wid = t >> 5, lane = t & 31;
    if (lane == 0) { red0[wid] = s; red1[wid] = ss; }
    __syncthreads();
    if (t == 0) {
        float a = 0.f, b2 = 0.f;
        #pragma unroll
        for (int i = 0; i < 8; i++) { a += red0[i]; b2 += red1[i]; }
        float mean = a * (1.0f / DD);
        float var  = b2 * (1.0f / DD) - mean * mean;
        smean = mean;
        srstd = rsqrtf(var + 1e-5f);
    }
    __syncthreads();
    float m = smean, r = srstd;
    float y0 = (v0 - m) * r * g[t]       + be[t];
    float y1 = (v1 - m) * r * g[t + 256] + be[t + 256];
    __nv_bfloat16 h0 = __float2bfloat16(y0);
    __nv_bfloat16 h1 = __float2bfloat16(y1);
    size_t o0 = (size_t)row * DD + t;
    oh[o0]       = h0;
    oh[o0 + 256] = h1;
    ol[o0]       = __float2bfloat16(y0 - __bfloat162float(h0));
    ol[o0 + 256] = __float2bfloat16(y1 - __bfloat162float(h1));
}

// ---------------------------------------------------------------------------
extern "C" void kernel_launch(void* const* d_in, const int* in_sizes, int n_in,
                              void* d_out, int out_size)
{
    const float* x   = (const float*)d_in[0];
    const float* wq  = (const float*)d_in[1];
    const float* bq  = (const float*)d_in[2];
    const float* wk  = (const float*)d_in[3];
    const float* bk  = (const float*)d_in[4];
    const float* wv  = (const float*)d_in[5];
    const float* bv  = (const float*)d_in[6];
    const float* wo  = (const float*)d_in[7];
    const float* bo  = (const float*)d_in[8];
    const float* g1  = (const float*)d_in[9];
    const float* be1 = (const float*)d_in[10];
    const float* g2  = (const float*)d_in[11];
    const float* be2 = (const float*)d_in[12];
    const float* w1  = (const float*)d_in[13];
    const float* bf1 = (const float*)d_in[14];
    const float* w2  = (const float*)d_in[15];
    const float* bf2 = (const float*)d_in[16];
    const float* rel = (const float*)d_in[17];
    float* out = (float*)d_out;

    float *v, *x1;
    __nv_bfloat16 *qh, *ql, *kh, *kl;
    __nv_bfloat16 *xnh, *xnl, *xn2h, *xn2l, *ath, *atl, *ffh, *ffl;
    __nv_bfloat16 *wqkvh, *wqkvl, *woh, *wol, *w1h, *w1l, *w2h, *w2l;
    cudaGetSymbolAddress((void**)&v,      g_v);
    cudaGetSymbolAddress((void**)&x1,     g_x1);
    cudaGetSymbolAddress((void**)&qh,     g_qb_h);
    cudaGetSymbolAddress((void**)&ql,     g_qb_l);
    cudaGetSymbolAddress((void**)&kh,     g_kb_h);
    cudaGetSymbolAddress((void**)&kl,     g_kb_l);
    cudaGetSymbolAddress((void**)&xnh,    g_xnb_h);
    cudaGetSymbolAddress((void**)&xnl,    g_xnb_l);
    cudaGetSymbolAddress((void**)&xn2h,   g_xn2b_h);
    cudaGetSymbolAddress((void**)&xn2l,   g_xn2b_l);
    cudaGetSymbolAddress((void**)&ath,    g_attnb_h);
    cudaGetSymbolAddress((void**)&atl,    g_attnb_l);
    cudaGetSymbolAddress((void**)&ffh,    g_ffb_h);
    cudaGetSymbolAddress((void**)&ffl,    g_ffb_l);
    cudaGetSymbolAddress((void**)&wqkvh,  g_wqkv_h);
    cudaGetSymbolAddress((void**)&wqkvl,  g_wqkv_l);
    cudaGetSymbolAddress((void**)&woh,    g_wto_h);
    cudaGetSymbolAddress((void**)&wol,    g_wto_l);
    cudaGetSymbolAddress((void**)&w1h,    g_wt1_h);
    cudaGetSymbolAddress((void**)&w1l,    g_wt1_l);
    cudaGetSymbolAddress((void**)&w2h,    g_wt2_h);
    cudaGetSymbolAddress((void**)&w2l,    g_wt2_l);

    const int SMEM_GEMM = 2 * BUFB;   // 81920
    cudaFuncSetAttribute(gemm_mma<1>, cudaFuncAttributeMaxDynamicSharedMemorySize, SMEM_GEMM);
    cudaFuncSetAttribute(gemm_mma<2>, cudaFuncAttributeMaxDynamicSharedMemorySize, SMEM_GEMM);
    cudaFuncSetAttribute(gemm_qkv,    cudaFuncAttributeMaxDynamicSharedMemorySize, SMEM_GEMM);
    cudaFuncSetAttribute(attn_fused,  cudaFuncAttributeMaxDynamicSharedMemorySize, FA_SMEM);

    dim3 gD(DD / 128, ROWS / 128);      // 4 x 64
    dim3 gQKV(3 * DD / 128, ROWS / 128);// 12 x 64
    dim3 gF(DFF / 128, ROWS / 128);     // 16 x 64

    // weight converts
    wconv<<<dim3(DD / 32, DD / 32), 256>>>(wq, wqkvh,               wqkvl,               DD, DD);
    wconv<<<dim3(DD / 32, DD / 32), 256>>>(wk, wqkvh + DD * DD,     wqkvl + DD * DD,     DD, DD);
    wconv<<<dim3(DD / 32, DD / 32), 256>>>(wv, wqkvh + 2 * DD * DD, wqkvl + 2 * DD * DD, DD, DD);
    wconv<<<dim3(DD / 32, DD / 32), 256>>>(wo, woh, wol, DD, DD);
    // LN1
    ln_kernel<<<ROWS, 256>>>(x, g1, be1, xnh, xnl);
    // fused QKV projection
    gemm_qkv<<<gQKV, 256, SMEM_GEMM>>>(xnh, xnl, wqkvh, wqkvl,
                                       bq, bk, bv, qh, ql, kh, kl, v);
    // FFN weight converts (independent)
    wconv<<<dim3(DD / 32, DFF / 32), 256>>>(w1, w1h, w1l, DD, DFF);
    wconv<<<dim3(DFF / 32, DD / 32), 256>>>(w2, w2h, w2l, DFF, DD);
    // fused logits + top-16 + softmax + A*V
    attn_fused<<<dim3(NN / 32, BB * HH), 256, FA_SMEM>>>(qh, ql, kh, kl, rel, v, ath, atl);
    // output projection + residual
    gemm_mma<1><<<gD, 256, SMEM_GEMM>>>(ath, atl, woh, wol, bo, x, x1, nullptr, ROWS, DD, DD);
    // LN2
    ln_kernel<<<ROWS, 256>>>(x1, g2, be2, xn2h, xn2l);
    // FFN up + exact GELU
    gemm_mma<2><<<gF, 256, SMEM_GEMM>>>(xn2h, xn2l, w1h, w1l, bf1, nullptr, ffh, ffl, ROWS, DFF, DD);
    // FFN down + residual -> output
    gemm_mma<1><<<gD, 256, SMEM_GEMM>>>(ffh, ffl, w2h, w2l, bf2, x1, out, nullptr, ROWS, DD, DFF);
}

// round 11
// speedup vs baseline: 1.3664x; 1.3664x over previous
#include <cuda_runtime.h>
#include <cuda_bf16.h>
#include <cuda_fp16.h>
#include <math.h>
#include <stdint.h>

#define BB   16
#define NN   512
#define DD   512
#define HH   8
#define KTOP 16
#define HD   64
#define MSL  512
#define ROWS (BB*NN)     // 8192
#define DFF  2048

// ---------------- scratch (static device memory; no allocs allowed) ----------
__device__ float g_v    [ROWS*DD];
__device__ float g_logits[(size_t)BB*HH*NN*NN];   // 134 MB
__device__ float g_x1   [ROWS*DD];

__device__ __nv_bfloat16 g_qb_h  [ROWS*DD];
__device__ __nv_bfloat16 g_qb_l  [ROWS*DD];
__device__ __nv_bfloat16 g_kb_h  [ROWS*DD];
__device__ __nv_bfloat16 g_kb_l  [ROWS*DD];
__device__ __nv_bfloat16 g_xnb_h  [ROWS*DD];
__device__ __nv_bfloat16 g_xnb_l  [ROWS*DD];
__device__ __nv_bfloat16 g_attnb_h[ROWS*DD];
__device__ __nv_bfloat16 g_attnb_l[ROWS*DD];
__device__ __nv_bfloat16 g_wqkv_h [3*DD*DD];      // packed Q|K|V, [1536][512]
__device__ __nv_bfloat16 g_wqkv_l [3*DD*DD];
__device__ __nv_bfloat16 g_wto_h  [DD*DD];
__device__ __nv_bfloat16 g_wto_l  [DD*DD];

__device__ __half g_xn2f [ROWS*DD];               // LN2 out (fp16)
__device__ __half g_fff  [(size_t)ROWS*DFF];      // FFN hidden (fp16)
__device__ __half g_w1f  [(size_t)DD*DFF];        // w1^T fp16 [2048][512]
__device__ __half g_w2f  [(size_t)DFF*DD];        // w2^T fp16 [512][2048]

// ================= PTX helpers (base sm_103 target legal) ====================
__device__ __forceinline__ uint32_t smem_u32(const void* p) {
    uint32_t a;
    asm("{ .reg .u64 t; cvta.to.shared.u64 t, %1; cvt.u32.u64 %0, t; }" : "=r"(a) : "l"(p));
    return a;
}
__device__ __forceinline__ void cpa16(uint32_t dst, const void* src) {
    asm volatile("cp.async.cg.shared.global [%0], [%1], 16;" :: "r"(dst), "l"(src));
}
__device__ __forceinline__ void cpa_commit() {
    asm volatile("cp.async.commit_group;" ::: "memory");
}
template<int N>
__device__ __forceinline__ void cpa_wait() {
    asm volatile("cp.async.wait_group %0;" :: "n"(N) : "memory");
}
__device__ __forceinline__ void ldsm4(uint32_t* r, uint32_t addr) {
    asm volatile("ldmatrix.sync.aligned.m8n8.x4.shared.b16 {%0,%1,%2,%3}, [%4];"
                 : "=r"(r[0]), "=r"(r[1]), "=r"(r[2]), "=r"(r[3]) : "r"(addr));
}
__device__ __forceinline__ void mma16816(float* c, const uint32_t* a, const uint32_t* b) {
    asm volatile(
        "mma.sync.aligned.m16n8k16.row.col.f32.bf16.bf16.f32 "
        "{%0,%1,%2,%3}, {%4,%5,%6,%7}, {%8,%9}, {%0,%1,%2,%3};"
        : "+f"(c[0]), "+f"(c[1]), "+f"(c[2]), "+f"(c[3])
        : "r"(a[0]), "r"(a[1]), "r"(a[2]), "r"(a[3]), "r"(b[0]), "r"(b[1]));
}
__device__ __forceinline__ void mma16816h(float* c, const uint32_t* a, const uint32_t* b) {
    asm volatile(
        "mma.sync.aligned.m16n8k16.row.col.f32.f16.f16.f32 "
        "{%0,%1,%2,%3}, {%4,%5,%6,%7}, {%8,%9}, {%0,%1,%2,%3};"
        : "+f"(c[0]), "+f"(c[1]), "+f"(c[2]), "+f"(c[3])
        : "r"(a[0]), "r"(a[1]), "r"(a[2]), "r"(a[3]), "r"(b[0]), "r"(b[1]));
}

#define LDA 40                         // padded smem row (elements)
#define TILEB (128 * LDA * 2)          // 10240 bytes per tile
#define BUFB  (4 * TILEB)              // Ah,Al,Bh,Bl per buffer (bf16x3)
#define BUF2  (2 * TILEB)              // A,B per buffer (fp16)

// ======= shared mainloop: bf16x3 triple-mma over K, double-buffered =========
#define GEMM_CORE(APH, APL, BPH, BPL, STRIDE, SCOUNT)                          \
    int r0 = tid >> 2, c0 = (tid & 3) * 8;                                     \
    int r1 = r0 + 64;                                                          \
    uint32_t off0 = (uint32_t)(r0 * LDA + c0) * 2;                             \
    uint32_t off1 = (uint32_t)(r1 * LDA + c0) * 2;                             \
    auto load_stage = [&](int s, int buf) {                                    \
        int k0 = s * 32;                                                       \
        uint32_t b = sbase + buf * BUFB;                                       \
        cpa16(b             + off0, APH + (size_t)r0 * STRIDE + k0 + c0);      \
        cpa16(b             + off1, APH + (size_t)r1 * STRIDE + k0 + c0);      \
        cpa16(b + TILEB     + off0, APL + (size_t)r0 * STRIDE + k0 + c0);      \
        cpa16(b + TILEB     + off1, APL + (size_t)r1 * STRIDE + k0 + c0);      \
        cpa16(b + 2 * TILEB + off0, BPH + (size_t)r0 * STRIDE + k0 + c0);      \
        cpa16(b + 2 * TILEB + off1, BPH + (size_t)r1 * STRIDE + k0 + c0);      \
        cpa16(b + 3 * TILEB + off0, BPL + (size_t)r0 * STRIDE + k0 + c0);      \
        cpa16(b + 3 * TILEB + off1, BPL + (size_t)r1 * STRIDE + k0 + c0);      \
    };                                                                         \
    load_stage(0, 0);                                                          \
    cpa_commit();                                                              \
    uint32_t a_off[2], b_off[4];                                               \
    _Pragma("unroll")                                                          \
    for (int mt = 0; mt < 2; mt++) {                                           \
        int row = wr * 32 + mt * 16 + (lane & 15);                             \
        a_off[mt] = (uint32_t)(row * LDA + (lane >> 4) * 8) * 2;               \
    }                                                                          \
    _Pragma("unroll")                                                          \
    for (int nt = 0; nt < 4; nt++) {                                           \
        int nrow = wc * 64 + nt * 16 + (lane & 7) + ((lane >> 4) & 1) * 8;     \
        b_off[nt] = (uint32_t)(nrow * LDA + ((lane >> 3) & 1) * 8) * 2;        \
    }                                                                          \
    for (int s = 0; s < SCOUNT; s++) {                                         \
        int buf = s & 1;                                                       \
        if (s + 1 < SCOUNT) { load_stage(s + 1, buf ^ 1); cpa_commit(); cpa_wait<1>(); } \
        else               { cpa_wait<0>(); }                                  \
        __syncthreads();                                                       \
        uint32_t ah = sbase + buf * BUFB;                                      \
        uint32_t al = ah + TILEB;                                              \
        uint32_t bh = ah + 2 * TILEB;                                          \
        uint32_t bl = ah + 3 * TILEB;                                          \
        _Pragma("unroll")                                                      \
        for (int kk = 0; kk < 2; kk++) {                                       \
            uint32_t afh[2][4], afl[2][4];                                     \
            _Pragma("unroll")                                                  \
            for (int mt = 0; mt < 2; mt++) {                                   \
                ldsm4(afh[mt], ah + a_off[mt] + kk * 32);                      \
                ldsm4(afl[mt], al + a_off[mt] + kk * 32);                      \
            }                                                                  \
            _Pragma("unroll")                                                  \
            for (int nt = 0; nt < 4; nt++) {                                   \
                uint32_t bfh[4], bfl[4];                                       \
                ldsm4(bfh, bh + b_off[nt] + kk * 32);                          \
                ldsm4(bfl, bl + b_off[nt] + kk * 32);                          \
                _Pragma("unroll")                                              \
                for (int mt = 0; mt < 2; mt++) {                               \
                    mma16816(acc[mt][nt * 2 + 0], afh[mt], bfh + 0);           \
                    mma16816(acc[mt][nt * 2 + 1], afh[mt], bfh + 2);           \
                    mma16816(acc[mt][nt * 2 + 0], afl[mt], bfh + 0);           \
                    mma16816(acc[mt][nt * 2 + 1], afl[mt], bfh + 2);           \
                    mma16816(acc[mt][nt * 2 + 0], afh[mt], bfl + 0);           \
                    mma16816(acc[mt][nt * 2 + 1], afh[mt], bfl + 2);           \
                }                                                              \
            }                                                                  \
        }                                                                      \
        __syncthreads();                                                       \
    }

#define ACC_INIT                                                               \
    float acc[2][8][4];                                                        \
    _Pragma("unroll")                                                          \
    for (int i = 0; i < 2; i++)                                                \
        _Pragma("unroll")                                                      \
        for (int j = 0; j < 8; j++)                                            \
            _Pragma("unroll")                                                  \
            for (int q = 0; q < 4; q++) acc[i][j][q] = 0.f;

// ================= bf16x3 GEMM, 128x128 tile ================================
// MODE 1: C(fp32) = acc + bias + res
template<int MODE>
__global__ void __launch_bounds__(256, 2) gemm_mma(
    const __nv_bfloat16* __restrict__ Ah, const __nv_bfloat16* __restrict__ Al,
    const __nv_bfloat16* __restrict__ Bh, const __nv_bfloat16* __restrict__ Bl,
    const float* __restrict__ bias, const float* __restrict__ res,
    void* __restrict__ Cout, int M, int N, int Kd)
{
    extern __shared__ char smem[];
    uint32_t sbase = smem_u32(smem);
    int tid = threadIdx.x, wid = tid >> 5, lane = tid & 31;
    int n0 = blockIdx.x * 128, m0 = blockIdx.y * 128;
    int wr = wid & 3, wc = wid >> 2;

    const __nv_bfloat16* Aph = Ah + (size_t)m0 * Kd;
    const __nv_bfloat16* Apl = Al + (size_t)m0 * Kd;
    const __nv_bfloat16* Bph = Bh + (size_t)n0 * Kd;
    const __nv_bfloat16* Bpl = Bl + (size_t)n0 * Kd;

    ACC_INIT;
    int S = Kd >> 5;
    GEMM_CORE(Aph, Apl, Bph, Bpl, Kd, S);

    int gr = lane >> 2, tg = lane & 3;
    #pragma unroll
    for (int mt = 0; mt < 2; mt++) {
        int rbase = m0 + wr * 32 + mt * 16 + gr;
        #pragma unroll
        for (int j = 0; j < 8; j++) {
            int col = n0 + wc * 64 + j * 8 + tg * 2;
            #pragma unroll
            for (int half2_ = 0; half2_ < 2; half2_++) {
                int row = rbase + half2_ * 8;
                float v0 = acc[mt][j][half2_ * 2 + 0] + bias[col];
                float v1 = acc[mt][j][half2_ * 2 + 1] + bias[col + 1];
                const float* rr = res + (size_t)row * N + col;
                float2 o; o.x = v0 + rr[0]; o.y = v1 + rr[1];
                *(float2*)((float*)Cout + (size_t)row * N + col) = o;
            }
        }
    }
}

// ================= fused QKV GEMM: N=1536 packed, mixed epilogue ============
__global__ void __launch_bounds__(256, 2) gemm_qkv(
    const __nv_bfloat16* __restrict__ Ah, const __nv_bfloat16* __restrict__ Al,
    const __nv_bfloat16* __restrict__ Bh, const __nv_bfloat16* __restrict__ Bl,
    const float* __restrict__ bq, const float* __restrict__ bk,
    const float* __restrict__ bv,
    __nv_bfloat16* __restrict__ qh, __nv_bfloat16* __restrict__ ql,
    __nv_bfloat16* __restrict__ kh, __nv_bfloat16* __restrict__ kl,
    float* __restrict__ v)
{
    extern __shared__ char smem[];
    uint32_t sbase = smem_u32(smem);
    int tid = threadIdx.x, wid = tid >> 5, lane = tid & 31;
    int n0 = blockIdx.x * 128, m0 = blockIdx.y * 128;
    int wr = wid & 3, wc = wid >> 2;

    const __nv_bfloat16* Aph = Ah + (size_t)m0 * DD;
    const __nv_bfloat16* Apl = Al + (size_t)m0 * DD;
    const __nv_bfloat16* Bph = Bh + (size_t)n0 * DD;
    const __nv_bfloat16* Bpl = Bl + (size_t)n0 * DD;

    ACC_INIT;
    GEMM_CORE(Aph, Apl, Bph, Bpl, DD, 16);

    int gr = lane >> 2, tg = lane & 3;
    int sel = n0 >> 9;                       // 0=Q, 1=K, 2=V
    const float* bias = (sel == 0) ? bq : (sel == 1) ? bk : bv;
    __nv_bfloat16* oh = (sel == 0) ? qh : kh;
    __nv_bfloat16* ol = (sel == 0) ? ql : kl;
    int nloc = n0 & 511;
    #pragma unroll
    for (int mt = 0; mt < 2; mt++) {
        int rbase = m0 + wr * 32 + mt * 16 + gr;
        #pragma unroll
        for (int j = 0; j < 8; j++) {
            int col = nloc + wc * 64 + j * 8 + tg * 2;
            #pragma unroll
            for (int half2_ = 0; half2_ < 2; half2_++) {
                int row = rbase + half2_ * 8;
                float v0 = acc[mt][j][half2_ * 2 + 0] + bias[col];
                float v1 = acc[mt][j][half2_ * 2 + 1] + bias[col + 1];
                if (sel == 2) {
                    float2 o; o.x = v0; o.y = v1;
                    *(float2*)(v + (size_t)row * DD + col) = o;
                } else {
                    __nv_bfloat162 ph, pl;
                    ph.x = __float2bfloat16(v0);
                    ph.y = __float2bfloat16(v1);
                    pl.x = __float2bfloat16(v0 - __bfloat162float(ph.x));
                    pl.y = __float2bfloat16(v1 - __bfloat162float(ph.y));
                    *(__nv_bfloat162*)(oh + (size_t)row * DD + col) = ph;
                    *(__nv_bfloat162*)(ol + (size_t)row * DD + col) = pl;
                }
            }
        }
    }
}

// ============ logits: bf16x3 HMMA, per (b,h), 128x128 tile, Kd=64 ===========
__global__ void __launch_bounds__(256, 2) logits_mma(
    const __nv_bfloat16* __restrict__ Qh, const __nv_bfloat16* __restrict__ Ql,
    const __nv_bfloat16* __restrict__ Kh, const __nv_bfloat16* __restrict__ Kl,
    const float* __restrict__ rel, float* __restrict__ logits)
{
    extern __shared__ char smem[];
    uint32_t sbase = smem_u32(smem);
    int tid = threadIdx.x, wid = tid >> 5, lane = tid & 31;
    int bh2 = blockIdx.z;
    int b = bh2 >> 3, h = bh2 & 7;
    int n0 = blockIdx.x * 128;
    int m0 = blockIdx.y * 128;
    int wr = wid & 3, wc = wid >> 2;

    const __nv_bfloat16* Aph = Qh + ((size_t)(b * NN + m0)) * DD + h * HD;
    const __nv_bfloat16* Apl = Ql + ((size_t)(b * NN + m0)) * DD + h * HD;
    const __nv_bfloat16* Bph = Kh + ((size_t)(b * NN + n0)) * DD + h * HD;
    const __nv_bfloat16* Bpl = Kl + ((size_t)(b * NN + n0)) * DD + h * HD;

    ACC_INIT;
    GEMM_CORE(Aph, Apl, Bph, Bpl, DD, 2);

    float* lbase = logits + (size_t)bh2 * NN * NN;
    int gr = lane >> 2, tg = lane & 3;
    #pragma unroll
    for (int mt = 0; mt < 2; mt++) {
        int rbase = m0 + wr * 32 + mt * 16 + gr;
        #pragma unroll
        for (int j = 0; j < 8; j++) {
            int col = n0 + wc * 64 + j * 8 + tg * 2;
            #pragma unroll
            for (int half2_ = 0; half2_ < 2; half2_++) {
                int row = rbase + half2_ * 8;
                float2 o;
                o.x = acc[mt][j][half2_ * 2 + 0] * 0.125f + rel[(col + 0 - row + MSL - 1) * HH + h];
                o.y = acc[mt][j][half2_ * 2 + 1] * 0.125f + rel[(col + 1 - row + MSL - 1) * HH + h];
                *(float2*)(lbase + (size_t)row * NN + col) = o;
            }
        }
    }
}

// ================= fp16 single-mma GEMM (FFN), 128x128 tile =================
// MODE 0: half = gelu(acc + bias)    MODE 1: fp32 = acc + bias + res
template<int MODE>
__global__ void __launch_bounds__(256, 2) gemm_fp16(
    const __half* __restrict__ A, const __half* __restrict__ Bt,
    const float* __restrict__ bias, const float* __restrict__ res,
    void* __restrict__ Cout, int N, int Kd)
{
    extern __shared__ char smem[];
    uint32_t sbase = smem_u32(smem);
    int tid = threadIdx.x, wid = tid >> 5, lane = tid & 31;
    int n0 = blockIdx.x * 128, m0 = blockIdx.y * 128;
    int wr = wid & 3, wc = wid >> 2;

    const __half* Ap = A + (size_t)m0 * Kd;
    const __half* Bp = Bt + (size_t)n0 * Kd;

    ACC_INIT;

    int r0 = tid >> 2, c0 = (tid & 3) * 8;
    int r1 = r0 + 64;
    uint32_t off0 = (uint32_t)(r0 * LDA + c0) * 2;
    uint32_t off1 = (uint32_t)(r1 * LDA + c0) * 2;
    auto load_stage = [&](int s, int buf) {
        int k0 = s * 32;
        uint32_t b = sbase + buf * BUF2;
        cpa16(b         + off0, Ap + (size_t)r0 * Kd + k0 + c0);
        cpa16(b         + off1, Ap + (size_t)r1 * Kd + k0 + c0);
        cpa16(b + TILEB + off0, Bp + (size_t)r0 * Kd + k0 + c0);
        cpa16(b + TILEB + off1, Bp + (size_t)r1 * Kd + k0 + c0);
    };
    int S = Kd >> 5;
    load_stage(0, 0);
    cpa_commit();

    uint32_t a_off[2], b_off[4];
    #pragma unroll
    for (int mt = 0; mt < 2; mt++) {
        int row = wr * 32 + mt * 16 + (lane & 15);
        a_off[mt] = (uint32_t)(row * LDA + (lane >> 4) * 8) * 2;
    }
    #pragma unroll
    for (int nt = 0; nt < 4; nt++) {
        int nrow = wc * 64 + nt * 16 + (lane & 7) + ((lane >> 4) & 1) * 8;
        b_off[nt] = (uint32_t)(nrow * LDA + ((lane >> 3) & 1) * 8) * 2;
    }

    for (int s = 0; s < S; s++) {
        int buf = s & 1;
        if (s + 1 < S) { load_stage(s + 1, buf ^ 1); cpa_commit(); cpa_wait<1>(); }
        else          { cpa_wait<0>(); }
        __syncthreads();

        uint32_t ab = sbase + buf * BUF2;
        uint32_t bb = ab + TILEB;
        #pragma unroll
        for (int kk = 0; kk < 2; kk++) {
            uint32_t af[2][4];
            #pragma unroll
            for (int mt = 0; mt < 2; mt++) ldsm4(af[mt], ab + a_off[mt] + kk * 32);
            #pragma unroll
            for (int nt = 0; nt < 4; nt++) {
                uint32_t bf[4];
                ldsm4(bf, bb + b_off[nt] + kk * 32);
                #pragma unroll
                for (int mt = 0; mt < 2; mt++) {
                    mma16816h(acc[mt][nt * 2 + 0], af[mt], bf + 0);
                    mma16816h(acc[mt][nt * 2 + 1], af[mt], bf + 2);
                }
            }
        }
        __syncthreads();
    }

    int gr = lane >> 2, tg = lane & 3;
    #pragma unroll
    for (int mt = 0; mt < 2; mt++) {
        int rbase = m0 + wr * 32 + mt * 16 + gr;
        #pragma unroll
        for (int j = 0; j < 8; j++) {
            int col = n0 + wc * 64 + j * 8 + tg * 2;
            #pragma unroll
            for (int half2_ = 0; half2_ < 2; half2_++) {
                int row = rbase + half2_ * 8;
                float v0 = acc[mt][j][half2_ * 2 + 0] + bias[col];
                float v1 = acc[mt][j][half2_ * 2 + 1] + bias[col + 1];
                if (MODE == 0) {
                    v0 = 0.5f * v0 * (1.0f + erff(v0 * 0.70710678118654752f));
                    v1 = 0.5f * v1 * (1.0f + erff(v1 * 0.70710678118654752f));
                    __half2 p;
                    p.x = __float2half_rn(v0);
                    p.y = __float2half_rn(v1);
                    *(__half2*)((__half*)Cout + (size_t)row * N + col) = p;
                } else {
                    const float* rr = res + (size_t)row * N + col;
                    float2 o; o.x = v0 + rr[0]; o.y = v1 + rr[1];
                    *(float2*)((float*)Cout + (size_t)row * N + col) = o;
                }
            }
        }
    }
}

// ========== prep: all weight transposes/converts in ONE launch ==============
// grid (16,16,12): z 0-3 = wq/wk/wv/wo (bf16 hi/lo), z 4-7 = w1 (fp16),
// z 8-11 = w2 (fp16). Each z handles a 512K x 512N sub-block.
__global__ void __launch_bounds__(256) prep_weights(
    const float* __restrict__ wq, const float* __restrict__ wk,
    const float* __restrict__ wv, const float* __restrict__ wo,
    const float* __restrict__ w1, const float* __restrict__ w2,
    __nv_bfloat16* __restrict__ wqkvh, __nv_bfloat16* __restrict__ wqkvl,
    __nv_bfloat16* __restrict__ woh,   __nv_bfloat16* __restrict__ wol,
    __half* __restrict__ w1f, __half* __restrict__ w2f)
{
    __shared__ float t[32][33];
    int z = blockIdx.z;
    int tx = threadIdx.x & 31, ty = threadIdx.x >> 5;

    const float* w; int Nd; size_t kbase = 0, nbase = 0;
    if (z < 4)      { w = (z == 0) ? wq : (z == 1) ? wk : (z == 2) ? wv : wo; Nd = DD; }
    else if (z < 8) { w = w1; Nd = DFF; nbase = (size_t)(z - 4) * 512; }
    else            { w = w2; Nd = DD;  kbase = (size_t)(z - 8) * 512; }

    size_t k0 = kbase + blockIdx.x * 32;
    size_t n0 = nbase + blockIdx.y * 32;

    #pragma unroll
    for (int i = 0; i < 4; i++)
        t[ty + 8 * i][tx] = w[(k0 + ty + 8 * i) * Nd + n0 + tx];
    __syncthreads();
    #pragma unroll
    for (int i = 0; i < 4; i++) {
        float v = t[tx][ty + 8 * i];
        size_t nout = n0 + ty + 8 * i;
        size_t kout = k0 + tx;
        if (z < 4) {
            __nv_bfloat16 h = __float2bfloat16(v);
            __nv_bfloat16 l = __float2bfloat16(v - __bfloat162float(h));
            if (z < 3) {
                size_t o = ((size_t)z * DD + nout) * DD + kout;
                wqkvh[o] = h; wqkvl[o] = l;
            } else {
                size_t o = nout * DD + kout;
                woh[o] = h; wol[o] = l;
            }
        } else if (z < 8) {
            w1f[nout * DD + kout] = __float2half_rn(v);    // [2048][512]
        } else {
            w2f[nout * DFF + kout] = __float2half_rn(v);   // [512][2048]
        }
    }
}

// ---------------- LayerNorm -> bf16 hi/lo ------------------------------------
__global__ void __launch_bounds__(256) ln_kernel(
    const float* __restrict__ x, const float* __restrict__ g,
    const float* __restrict__ be, __nv_bfloat16* __restrict__ oh,
    __nv_bfloat16* __restrict__ ol)
{
    int row = blockIdx.x;
    const float* xr = x + (size_t)row * DD;
    int t = threadIdx.x;
    float v0 = xr[t], v1 = xr[t + 256];
    float s = v0 + v1, ss = v0 * v0 + v1 * v1;
    #pragma unroll
    for (int o = 16; o; o >>= 1) {
        s  += __shfl_xor_sync(0xFFFFFFFFu, s,  o);
        ss += __shfl_xor_sync(0xFFFFFFFFu, ss, o);
    }
    __shared__ float red0[8], red1[8];
    __shared__ float smean, srstd;
    int wid = t >> 5, lane = t & 31;
    if (lane == 0) { red0[wid] = s; red1[wid] = ss; }
    __syncthreads();
    if (t == 0) {
        float a = 0.f, b2 = 0.f;
        #pragma unroll
        for (int i = 0; i < 8; i++) { a += red0[i]; b2 += red1[i]; }
        float mean = a * (1.0f / DD);
        float var  = b2 * (1.0f / DD) - mean * mean;
        smean = mean;
        srstd = rsqrtf(var + 1e-5f);
    }
    __syncthreads();
    float m = smean, r = srstd;
    float y0 = (v0 - m) * r * g[t]       + be[t];
    float y1 = (v1 - m) * r * g[t + 256] + be[t + 256];
    __nv_bfloat16 h0 = __float2bfloat16(y0);
    __nv_bfloat16 h1 = __float2bfloat16(y1);
    size_t o0 = (size_t)row * DD + t;
    oh[o0]       = h0;
    oh[o0 + 256] = h1;
    ol[o0]       = __float2bfloat16(y0 - __bfloat162float(h0));
    ol[o0 + 256] = __float2bfloat16(y1 - __bfloat162float(h1));
}

// ---------------- LayerNorm -> fp16 (for FFN) --------------------------------
__global__ void __launch_bounds__(256) ln_fp16(
    const float* __restrict__ x, const float* __restrict__ g,
    const float* __restrict__ be, __half* __restrict__ out)
{
    int row = blockIdx.x;
    const float* xr = x + (size_t)row * DD;
    int t = threadIdx.x;
    float v0 = xr[t], v1 = xr[t + 256];
    float s = v0 + v1, ss = v0 * v0 + v1 * v1;
    #pragma unroll
    for (int o = 16; o; o >>= 1) {
        s  += __shfl_xor_sync(0xFFFFFFFFu, s,  o);
        ss += __shfl_xor_sync(0xFFFFFFFFu, ss, o);
    }
    __shared__ float red0[8], red1[8];
    __shared__ float smean, srstd;
    int wid = t >> 5, lane = t & 31;
    if (lane == 0) { red0[wid] = s; red1[wid] = ss; }
    __syncthreads();
    if (t == 0) {
        float a = 0.f, b2 = 0.f;
        #pragma unroll
        for (int i = 0; i < 8; i++) { a += red0[i]; b2 += red1[i]; }
        float mean = a * (1.0f / DD);
        float var  = b2 * (1.0f / DD) - mean * mean;
        smean = mean;
        srstd = rsqrtf(var + 1e-5f);
    }
    __syncthreads();
    float m = smean, r = srstd;
    out[(size_t)row * DD + t]       = __float2half_rn((v0 - m) * r * g[t]       + be[t]);
    out[(size_t)row * DD + t + 256] = __float2half_rn((v1 - m) * r * g[t + 256] + be[t + 256]);
}

// ---------------- top-16 + softmax + sparse A*V -> bf16 hi/lo ---------------
__global__ void __launch_bounds__(256) topk_kernel(
    const float* __restrict__ logits, const float* __restrict__ v,
    __nv_bfloat16* __restrict__ ah, __nv_bfloat16* __restrict__ al)
{
    int w = (blockIdx.x * blockDim.x + threadIdx.x) >> 5;
    int lane = threadIdx.x & 31;
    int n = w & (NN - 1);
    int h = (w >> 9) & 7;
    int b = w >> 12;

    const float* lrow = logits + (size_t)w * NN;
    float vals[16];
    #pragma unroll
    for (int t = 0; t < 16; t++) vals[t] = lrow[t * 32 + lane];

    unsigned mask = 0xFFFFu;
    float selv = 0.f;
    int   selm = 0;
    #pragma unroll
    for (int r = 0; r < 16; r++) {
        float bv = -INFINITY; int bs = 0;
        #pragma unroll
        for (int t = 0; t < 16; t++) {
            bool live = (mask >> t) & 1u;
            if (live && vals[t] > bv) { bv = vals[t]; bs = t; }
        }
        float rv = bv;
        int rm = bs * 32 + lane;
        #pragma unroll
        for (int off = 16; off; off >>= 1) {
            float ov = __shfl_xor_sync(0xFFFFFFFFu, rv, off);
            int   om = __shfl_xor_sync(0xFFFFFFFFu, rm, off);
            if (ov > rv || (ov == rv && om < rm)) { rv = ov; rm = om; }
        }
        if ((rm & 31) == lane) mask &= ~(1u << (rm >> 5));
        if (lane == r) { selv = rv; selm = rm; }
    }

    float maxv = __shfl_sync(0xFFFFFFFFu, selv, 0);
    float e = (lane < 16) ? expf(selv - maxv) : 0.f;
    float s = e;
    #pragma unroll
    for (int off = 16; off; off >>= 1) s += __shfl_xor_sync(0xFFFFFFFFu, s, off);
    float p = e / s;

    float o0 = 0.f, o1 = 0.f;
    const float* vbase = v + ((size_t)b * NN) * DD + h * HD;
    #pragma unroll
    for (int l = 0; l < 16; l++) {
        float pl = __shfl_sync(0xFFFFFFFFu, p, l);
        int   ml = __shfl_sync(0xFFFFFFFFu, selm, l);
        const float* vr = vbase + (size_t)ml * DD;
        o0 += pl * vr[lane];
        o1 += pl * vr[lane + 32];
    }
    size_t base = ((size_t)(b * NN + n)) * DD + h * HD;
    __nv_bfloat16 h0 = __float2bfloat16(o0);
    __nv_bfloat16 h1 = __float2bfloat16(o1);
    ah[base + lane]      = h0;
    ah[base + lane + 32] = h1;
    al[base + lane]      = __float2bfloat16(o0 - __bfloat162float(h0));
    al[base + lane + 32] = __float2bfloat16(o1 - __bfloat162float(h1));
}

// ---------------------------------------------------------------------------
extern "C" void kernel_launch(void* const* d_in, const int* in_sizes, int n_in,
                              void* d_out, int out_size)
{
    const float* x   = (const float*)d_in[0];
    const float* wq  = (const float*)d_in[1];
    const float* bq  = (const float*)d_in[2];
    const float* wk  = (const float*)d_in[3];
    const float* bk  = (const float*)d_in[4];
    const float* wv  = (const float*)d_in[5];
    const float* bv  = (const float*)d_in[6];
    const float* wo  = (const float*)d_in[7];
    const float* bo  = (const float*)d_in[8];
    const float* g1  = (const float*)d_in[9];
    const float* be1 = (const float*)d_in[10];
    const float* g2  = (const float*)d_in[11];
    const float* be2 = (const float*)d_in[12];
    const float* w1  = (const float*)d_in[13];
    const float* bf1 = (const float*)d_in[14];
    const float* w2  = (const float*)d_in[15];
    const float* bf2 = (const float*)d_in[16];
    const float* rel = (const float*)d_in[17];
    float* out = (float*)d_out;

    float *v, *logits, *x1;
    __nv_bfloat16 *qh, *ql, *kh, *kl, *xnh, *xnl, *ath, *atl;
    __nv_bfloat16 *wqkvh, *wqkvl, *woh, *wol;
    __half *xn2f, *fff, *w1f, *w2f;
    cudaGetSymbolAddress((void**)&v,      g_v);
    cudaGetSymbolAddress((void**)&logits, g_logits);
    cudaGetSymbolAddress((void**)&x1,     g_x1);
    cudaGetSymbolAddress((void**)&qh,     g_qb_h);
    cudaGetSymbolAddress((void**)&ql,     g_qb_l);
    cudaGetSymbolAddress((void**)&kh,     g_kb_h);
    cudaGetSymbolAddress((void**)&kl,     g_kb_l);
    cudaGetSymbolAddress((void**)&xnh,    g_xnb_h);
    cudaGetSymbolAddress((void**)&xnl,    g_xnb_l);
    cudaGetSymbolAddress((void**)&ath,    g_attnb_h);
    cudaGetSymbolAddress((void**)&atl,    g_attnb_l);
    cudaGetSymbolAddress((void**)&wqkvh,  g_wqkv_h);
    cudaGetSymbolAddress((void**)&wqkvl,  g_wqkv_l);
    cudaGetSymbolAddress((void**)&woh,    g_wto_h);
    cudaGetSymbolAddress((void**)&wol,    g_wto_l);
    cudaGetSymbolAddress((void**)&xn2f,   g_xn2f);
    cudaGetSymbolAddress((void**)&fff,    g_fff);
    cudaGetSymbolAddress((void**)&w1f,    g_w1f);
    cudaGetSymbolAddress((void**)&w2f,    g_w2f);

    const int SMEM_GEMM = 2 * BUFB;   // 81920
    const int SMEM_FP16 = 2 * BUF2;   // 40960
    cudaFuncSetAttribute(gemm_mma<1>,  cudaFuncAttributeMaxDynamicSharedMemorySize, SMEM_GEMM);
    cudaFuncSetAttribute(gemm_qkv,     cudaFuncAttributeMaxDynamicSharedMemorySize, SMEM_GEMM);
    cudaFuncSetAttribute(logits_mma,   cudaFuncAttributeMaxDynamicSharedMemorySize, SMEM_GEMM);
    cudaFuncSetAttribute(gemm_fp16<0>, cudaFuncAttributeMaxDynamicSharedMemorySize, SMEM_FP16);
    cudaFuncSetAttribute(gemm_fp16<1>, cudaFuncAttributeMaxDynamicSharedMemorySize, SMEM_FP16);

    dim3 gD(DD / 128, ROWS / 128);       // 4 x 64
    dim3 gQKV(3 * DD / 128, ROWS / 128); // 12 x 64
    dim3 gF(DFF / 128, ROWS / 128);      // 16 x 64

    // 1. all weight converts in one launch
    prep_weights<<<dim3(16, 16, 12), 256>>>(wq, wk, wv, wo, w1, w2,
                                            wqkvh, wqkvl, woh, wol, w1f, w2f);
    // 2. LN1 -> bf16 hi/lo
    ln_kernel<<<ROWS, 256>>>(x, g1, be1, xnh, xnl);
    // 3. fused QKV projection (bf16x3)
    gemm_qkv<<<gQKV, 256, SMEM_GEMM>>>(xnh, xnl, wqkvh, wqkvl,
                                       bq, bk, bv, qh, ql, kh, kl, v);
    // 4. logits + relative bias (bf16x3)
    logits_mma<<<dim3(NN / 128, NN / 128, BB * HH), 256, SMEM_GEMM>>>(qh, ql, kh, kl, rel, logits);
    // 5. top-16 -> softmax -> sparse A*V
    topk_kernel<<<(BB * HH * NN * 32) / 256, 256>>>(logits, v, ath, atl);
    // 6. output projection + residual (bf16x3)
    gemm_mma<1><<<gD, 256, SMEM_GEMM>>>(ath, atl, woh, wol, bo, x, x1, ROWS, DD, DD);
    // 7. LN2 -> fp16
    ln_fp16<<<ROWS, 256>>>(x1, g2, be2, xn2f);
    // 8. FFN up + exact GELU (fp16 x1) -> fp16
    gemm_fp16<0><<<gF, 256, SMEM_FP16>>>(xn2f, w1f, bf1, nullptr, fff, DFF, DD);
    // 9. FFN down + residual (fp16 x1) -> output
    gemm_fp16<1><<<gD, 256, SMEM_FP16>>>(fff, w2f, bf2, x1, out, DD, DFF);
}

// round 12
// speedup vs baseline: 1.4553x; 1.0651x over previous
#include <cuda_runtime.h>
#include <cuda_bf16.h>
#include <cuda_fp16.h>
#include <math.h>
#include <stdint.h>

#define BB   16
#define NN   512
#define DD   512
#define HH   8
#define KTOP 16
#define HD   64
#define MSL  512
#define ROWS (BB*NN)     // 8192
#define DFF  2048

// ---------------- scratch (static device memory; no allocs allowed) ----------
__device__ float g_v    [ROWS*DD];
__device__ float g_logits[(size_t)BB*HH*NN*NN];   // 134 MB
__device__ float g_x1   [ROWS*DD];

__device__ __nv_bfloat16 g_qb_h  [ROWS*DD];
__device__ __nv_bfloat16 g_qb_l  [ROWS*DD];
__device__ __nv_bfloat16 g_kb_h  [ROWS*DD];
__device__ __nv_bfloat16 g_kb_l  [ROWS*DD];
__device__ __nv_bfloat16 g_xnb_h  [ROWS*DD];
__device__ __nv_bfloat16 g_xnb_l  [ROWS*DD];
__device__ __nv_bfloat16 g_wqkv_h [3*DD*DD];      // packed Q|K|V, [1536][512]
__device__ __nv_bfloat16 g_wqkv_l [3*DD*DD];

__device__ __half g_attnf[ROWS*DD];               // attn out (fp16)
__device__ __half g_wof  [DD*DD];                 // wo^T fp16
__device__ __half g_xn2f [ROWS*DD];               // LN2 out (fp16)
__device__ __half g_fff  [(size_t)ROWS*DFF];      // FFN hidden (fp16)
__device__ __half g_w1f  [(size_t)DD*DFF];        // w1^T fp16 [2048][512]
__device__ __half g_w2f  [(size_t)DFF*DD];        // w2^T fp16 [512][2048]

// ================= PTX helpers (base sm_103 target legal) ====================
__device__ __forceinline__ uint32_t smem_u32(const void* p) {
    uint32_t a;
    asm("{ .reg .u64 t; cvta.to.shared.u64 t, %1; cvt.u32.u64 %0, t; }" : "=r"(a) : "l"(p));
    return a;
}
__device__ __forceinline__ void cpa16(uint32_t dst, const void* src) {
    asm volatile("cp.async.cg.shared.global [%0], [%1], 16;" :: "r"(dst), "l"(src));
}
__device__ __forceinline__ void cpa_commit() {
    asm volatile("cp.async.commit_group;" ::: "memory");
}
template<int N>
__device__ __forceinline__ void cpa_wait() {
    asm volatile("cp.async.wait_group %0;" :: "n"(N) : "memory");
}
__device__ __forceinline__ void ldsm4(uint32_t* r, uint32_t addr) {
    asm volatile("ldmatrix.sync.aligned.m8n8.x4.shared.b16 {%0,%1,%2,%3}, [%4];"
                 : "=r"(r[0]), "=r"(r[1]), "=r"(r[2]), "=r"(r[3]) : "r"(addr));
}
__device__ __forceinline__ void mma16816(float* c, const uint32_t* a, const uint32_t* b) {
    asm volatile(
        "mma.sync.aligned.m16n8k16.row.col.f32.bf16.bf16.f32 "
        "{%0,%1,%2,%3}, {%4,%5,%6,%7}, {%8,%9}, {%0,%1,%2,%3};"
        : "+f"(c[0]), "+f"(c[1]), "+f"(c[2]), "+f"(c[3])
        : "r"(a[0]), "r"(a[1]), "r"(a[2]), "r"(a[3]), "r"(b[0]), "r"(b[1]));
}
__device__ __forceinline__ void mma16816h(float* c, const uint32_t* a, const uint32_t* b) {
    asm volatile(
        "mma.sync.aligned.m16n8k16.row.col.f32.f16.f16.f32 "
        "{%0,%1,%2,%3}, {%4,%5,%6,%7}, {%8,%9}, {%0,%1,%2,%3};"
        : "+f"(c[0]), "+f"(c[1]), "+f"(c[2]), "+f"(c[3])
        : "r"(a[0]), "r"(a[1]), "r"(a[2]), "r"(a[3]), "r"(b[0]), "r"(b[1]));
}

#define LDA 40                         // padded smem row (elements)
#define TILEB (128 * LDA * 2)          // 10240 bytes per tile
#define BUFB  (4 * TILEB)              // Ah,Al,Bh,Bl per buffer (bf16x3)
#define BUF2  (2 * TILEB)              // A,B per buffer (fp16)

// ======= shared mainloop: bf16 mma over K, double-buffered ==================
// TRIPLE: acc += Ah*Bh + Al*Bh + Ah*Bl ; else acc += Ah*Bh only
#define GEMM_CORE(APH, APL, BPH, BPL, STRIDE, SCOUNT, TRIPLE)                  \
    int r0 = tid >> 2, c0 = (tid & 3) * 8;                                     \
    int r1 = r0 + 64;                                                          \
    uint32_t off0 = (uint32_t)(r0 * LDA + c0) * 2;                             \
    uint32_t off1 = (uint32_t)(r1 * LDA + c0) * 2;                             \
    auto load_stage = [&](int s, int buf) {                                    \
        int k0 = s * 32;                                                       \
        uint32_t b = sbase + buf * BUFB;                                       \
        cpa16(b             + off0, APH + (size_t)r0 * STRIDE + k0 + c0);      \
        cpa16(b             + off1, APH + (size_t)r1 * STRIDE + k0 + c0);      \
        cpa16(b + 2 * TILEB + off0, BPH + (size_t)r0 * STRIDE + k0 + c0);      \
        cpa16(b + 2 * TILEB + off1, BPH + (size_t)r1 * STRIDE + k0 + c0);      \
        if (TRIPLE) {                                                          \
            cpa16(b + TILEB     + off0, APL + (size_t)r0 * STRIDE + k0 + c0);  \
            cpa16(b + TILEB     + off1, APL + (size_t)r1 * STRIDE + k0 + c0);  \
            cpa16(b + 3 * TILEB + off0, BPL + (size_t)r0 * STRIDE + k0 + c0);  \
            cpa16(b + 3 * TILEB + off1, BPL + (size_t)r1 * STRIDE + k0 + c0);  \
        }                                                                      \
    };                                                                         \
    load_stage(0, 0);                                                          \
    cpa_commit();                                                              \
    uint32_t a_off[2], b_off[4];                                               \
    _Pragma("unroll")                                                          \
    for (int mt = 0; mt < 2; mt++) {                                           \
        int row = wr * 32 + mt * 16 + (lane & 15);                             \
        a_off[mt] = (uint32_t)(row * LDA + (lane >> 4) * 8) * 2;               \
    }                                                                          \
    _Pragma("unroll")                                                          \
    for (int nt = 0; nt < 4; nt++) {                                           \
        int nrow = wc * 64 + nt * 16 + (lane & 7) + ((lane >> 4) & 1) * 8;     \
        b_off[nt] = (uint32_t)(nrow * LDA + ((lane >> 3) & 1) * 8) * 2;        \
    }                                                                          \
    for (int s = 0; s < SCOUNT; s++) {                                         \
        int buf = s & 1;                                                       \
        if (s + 1 < SCOUNT) { load_stage(s + 1, buf ^ 1); cpa_commit(); cpa_wait<1>(); } \
        else               { cpa_wait<0>(); }                                  \
        __syncthreads();                                                       \
        uint32_t ah = sbase + buf * BUFB;                                      \
        uint32_t al = ah + TILEB;                                              \
        uint32_t bh = ah + 2 * TILEB;                                          \
        uint32_t bl = ah + 3 * TILEB;                                          \
        _Pragma("unroll")                                                      \
        for (int kk = 0; kk < 2; kk++) {                                       \
            uint32_t afh[2][4], afl[2][4];                                     \
            _Pragma("unroll")                                                  \
            for (int mt = 0; mt < 2; mt++) {                                   \
                ldsm4(afh[mt], ah + a_off[mt] + kk * 32);                      \
                if (TRIPLE) ldsm4(afl[mt], al + a_off[mt] + kk * 32);          \
            }                                                                  \
            _Pragma("unroll")                                                  \
            for (int nt = 0; nt < 4; nt++) {                                   \
                uint32_t bfh[4], bfl[4];                                       \
                ldsm4(bfh, bh + b_off[nt] + kk * 32);                          \
                if (TRIPLE) ldsm4(bfl, bl + b_off[nt] + kk * 32);              \
                _Pragma("unroll")                                              \
                for (int mt = 0; mt < 2; mt++) {                               \
                    mma16816(acc[mt][nt * 2 + 0], afh[mt], bfh + 0);           \
                    mma16816(acc[mt][nt * 2 + 1], afh[mt], bfh + 2);           \
                    if (TRIPLE) {                                              \
                        mma16816(acc[mt][nt * 2 + 0], afl[mt], bfh + 0);       \
                        mma16816(acc[mt][nt * 2 + 1], afl[mt], bfh + 2);       \
                        mma16816(acc[mt][nt * 2 + 0], afh[mt], bfl + 0);       \
                        mma16816(acc[mt][nt * 2 + 1], afh[mt], bfl + 2);       \
                    }                                                          \
                }                                                              \
            }                                                                  \
        }                                                                      \
        __syncthreads();                                                       \
    }

#define ACC_INIT                                                               \
    float acc[2][8][4];                                                        \
    _Pragma("unroll")                                                          \
    for (int i = 0; i < 2; i++)                                                \
        _Pragma("unroll")                                                      \
        for (int j = 0; j < 8; j++)                                            \
            _Pragma("unroll")                                                  \
            for (int q = 0; q < 4; q++) acc[i][j][q] = 0.f;

// ================= fused QKV GEMM: N=1536 packed, mixed epilogue ============
// Q,K blocks: bf16x3 (selection-critical). V blocks: single bf16 mma.
__global__ void __launch_bounds__(256, 2) gemm_qkv(
    const __nv_bfloat16* __restrict__ Ah, const __nv_bfloat16* __restrict__ Al,
    const __nv_bfloat16* __restrict__ Bh, const __nv_bfloat16* __restrict__ Bl,
    const float* __restrict__ bq, const float* __restrict__ bk,
    const float* __restrict__ bv,
    __nv_bfloat16* __restrict__ qh, __nv_bfloat16* __restrict__ ql,
    __nv_bfloat16* __restrict__ kh, __nv_bfloat16* __restrict__ kl,
    float* __restrict__ v)
{
    extern __shared__ char smem[];
    uint32_t sbase = smem_u32(smem);
    int tid = threadIdx.x, wid = tid >> 5, lane = tid & 31;
    int n0 = blockIdx.x * 128, m0 = blockIdx.y * 128;
    int wr = wid & 3, wc = wid >> 2;
    bool triple = (n0 < 1024);           // Q,K need hi/lo; V single

    const __nv_bfloat16* Aph = Ah + (size_t)m0 * DD;
    const __nv_bfloat16* Apl = Al + (size_t)m0 * DD;
    const __nv_bfloat16* Bph = Bh + (size_t)n0 * DD;
    const __nv_bfloat16* Bpl = Bl + (size_t)n0 * DD;

    ACC_INIT;
    GEMM_CORE(Aph, Apl, Bph, Bpl, DD, 16, triple);

    int gr = lane >> 2, tg = lane & 3;
    int sel = n0 >> 9;                       // 0=Q, 1=K, 2=V
    const float* bias = (sel == 0) ? bq : (sel == 1) ? bk : bv;
    __nv_bfloat16* oh = (sel == 0) ? qh : kh;
    __nv_bfloat16* ol = (sel == 0) ? ql : kl;
    int nloc = n0 & 511;
    #pragma unroll
    for (int mt = 0; mt < 2; mt++) {
        int rbase = m0 + wr * 32 + mt * 16 + gr;
        #pragma unroll
        for (int j = 0; j < 8; j++) {
            int col = nloc + wc * 64 + j * 8 + tg * 2;
            #pragma unroll
            for (int half2_ = 0; half2_ < 2; half2_++) {
                int row = rbase + half2_ * 8;
                float v0 = acc[mt][j][half2_ * 2 + 0] + bias[col];
                float v1 = acc[mt][j][half2_ * 2 + 1] + bias[col + 1];
                if (sel == 2) {
                    float2 o; o.x = v0; o.y = v1;
                    *(float2*)(v + (size_t)row * DD + col) = o;
                } else {
                    __nv_bfloat162 ph, pl;
                    ph.x = __float2bfloat16(v0);
                    ph.y = __float2bfloat16(v1);
                    pl.x = __float2bfloat16(v0 - __bfloat162float(ph.x));
                    pl.y = __float2bfloat16(v1 - __bfloat162float(ph.y));
                    *(__nv_bfloat162*)(oh + (size_t)row * DD + col) = ph;
                    *(__nv_bfloat162*)(ol + (size_t)row * DD + col) = pl;
                }
            }
        }
    }
}

// ============ logits: bf16x3 HMMA, per (b,h), 128x128 tile, Kd=64 ===========
__global__ void __launch_bounds__(256, 2) logits_mma(
    const __nv_bfloat16* __restrict__ Qh, const __nv_bfloat16* __restrict__ Ql,
    const __nv_bfloat16* __restrict__ Kh, const __nv_bfloat16* __restrict__ Kl,
    const float* __restrict__ rel, float* __restrict__ logits)
{
    extern __shared__ char smem[];
    uint32_t sbase = smem_u32(smem);
    int tid = threadIdx.x, wid = tid >> 5, lane = tid & 31;
    int bh2 = blockIdx.z;
    int b = bh2 >> 3, h = bh2 & 7;
    int n0 = blockIdx.x * 128;
    int m0 = blockIdx.y * 128;
    int wr = wid & 3, wc = wid >> 2;

    const __nv_bfloat16* Aph = Qh + ((size_t)(b * NN + m0)) * DD + h * HD;
    const __nv_bfloat16* Apl = Ql + ((size_t)(b * NN + m0)) * DD + h * HD;
    const __nv_bfloat16* Bph = Kh + ((size_t)(b * NN + n0)) * DD + h * HD;
    const __nv_bfloat16* Bpl = Kl + ((size_t)(b * NN + n0)) * DD + h * HD;

    ACC_INIT;
    GEMM_CORE(Aph, Apl, Bph, Bpl, DD, 2, true);

    float* lbase = logits + (size_t)bh2 * NN * NN;
    int gr = lane >> 2, tg = lane & 3;
    #pragma unroll
    for (int mt = 0; mt < 2; mt++) {
        int rbase = m0 + wr * 32 + mt * 16 + gr;
        #pragma unroll
        for (int j = 0; j < 8; j++) {
            int col = n0 + wc * 64 + j * 8 + tg * 2;
            #pragma unroll
            for (int half2_ = 0; half2_ < 2; half2_++) {
                int row = rbase + half2_ * 8;
                float2 o;
                o.x = acc[mt][j][half2_ * 2 + 0] * 0.125f + rel[(col + 0 - row + MSL - 1) * HH + h];
                o.y = acc[mt][j][half2_ * 2 + 1] * 0.125f + rel[(col + 1 - row + MSL - 1) * HH + h];
                *(float2*)(lbase + (size_t)row * NN + col) = o;
            }
        }
    }
}

// ================= fp16 single-mma GEMM, 128x128 tile =======================
// MODE 0: half = gelu(acc + bias)    MODE 1: fp32 = acc + bias + res
template<int MODE>
__global__ void __launch_bounds__(256, 2) gemm_fp16(
    const __half* __restrict__ A, const __half* __restrict__ Bt,
    const float* __restrict__ bias, const float* __restrict__ res,
    void* __restrict__ Cout, int N, int Kd)
{
    extern __shared__ char smem[];
    uint32_t sbase = smem_u32(smem);
    int tid = threadIdx.x, wid = tid >> 5, lane = tid & 31;
    int n0 = blockIdx.x * 128, m0 = blockIdx.y * 128;
    int wr = wid & 3, wc = wid >> 2;

    const __half* Ap = A + (size_t)m0 * Kd;
    const __half* Bp = Bt + (size_t)n0 * Kd;

    ACC_INIT;

    int r0 = tid >> 2, c0 = (tid & 3) * 8;
    int r1 = r0 + 64;
    uint32_t off0 = (uint32_t)(r0 * LDA + c0) * 2;
    uint32_t off1 = (uint32_t)(r1 * LDA + c0) * 2;
    auto load_stage = [&](int s, int buf) {
        int k0 = s * 32;
        uint32_t b = sbase + buf * BUF2;
        cpa16(b         + off0, Ap + (size_t)r0 * Kd + k0 + c0);
        cpa16(b         + off1, Ap + (size_t)r1 * Kd + k0 + c0);
        cpa16(b + TILEB + off0, Bp + (size_t)r0 * Kd + k0 + c0);
        cpa16(b + TILEB + off1, Bp + (size_t)r1 * Kd + k0 + c0);
    };
    int S = Kd >> 5;
    load_stage(0, 0);
    cpa_commit();

    uint32_t a_off[2], b_off[4];
    #pragma unroll
    for (int mt = 0; mt < 2; mt++) {
        int row = wr * 32 + mt * 16 + (lane & 15);
        a_off[mt] = (uint32_t)(row * LDA + (lane >> 4) * 8) * 2;
    }
    #pragma unroll
    for (int nt = 0; nt < 4; nt++) {
        int nrow = wc * 64 + nt * 16 + (lane & 7) + ((lane >> 4) & 1) * 8;
        b_off[nt] = (uint32_t)(nrow * LDA + ((lane >> 3) & 1) * 8) * 2;
    }

    for (int s = 0; s < S; s++) {
        int buf = s & 1;
        if (s + 1 < S) { load_stage(s + 1, buf ^ 1); cpa_commit(); cpa_wait<1>(); }
        else          { cpa_wait<0>(); }
        __syncthreads();

        uint32_t ab = sbase + buf * BUF2;
        uint32_t bb = ab + TILEB;
        #pragma unroll
        for (int kk = 0; kk < 2; kk++) {
            uint32_t af[2][4];
            #pragma unroll
            for (int mt = 0; mt < 2; mt++) ldsm4(af[mt], ab + a_off[mt] + kk * 32);
            #pragma unroll
            for (int nt = 0; nt < 4; nt++) {
                uint32_t bf[4];
                ldsm4(bf, bb + b_off[nt] + kk * 32);
                #pragma unroll
                for (int mt = 0; mt < 2; mt++) {
                    mma16816h(acc[mt][nt * 2 + 0], af[mt], bf + 0);
                    mma16816h(acc[mt][nt * 2 + 1], af[mt], bf + 2);
                }
            }
        }
        __syncthreads();
    }

    int gr = lane >> 2, tg = lane & 3;
    #pragma unroll
    for (int mt = 0; mt < 2; mt++) {
        int rbase = m0 + wr * 32 + mt * 16 + gr;
        #pragma unroll
        for (int j = 0; j < 8; j++) {
            int col = n0 + wc * 64 + j * 8 + tg * 2;
            #pragma unroll
            for (int half2_ = 0; half2_ < 2; half2_++) {
                int row = rbase + half2_ * 8;
                float v0 = acc[mt][j][half2_ * 2 + 0] + bias[col];
                float v1 = acc[mt][j][half2_ * 2 + 1] + bias[col + 1];
                if (MODE == 0) {
                    v0 = 0.5f * v0 * (1.0f + erff(v0 * 0.70710678118654752f));
                    v1 = 0.5f * v1 * (1.0f + erff(v1 * 0.70710678118654752f));
                    __half2 p;
                    p.x = __float2half_rn(v0);
                    p.y = __float2half_rn(v1);
                    *(__half2*)((__half*)Cout + (size_t)row * N + col) = p;
                } else {
                    const float* rr = res + (size_t)row * N + col;
                    float2 o; o.x = v0 + rr[0]; o.y = v1 + rr[1];
                    *(float2*)((float*)Cout + (size_t)row * N + col) = o;
                }
            }
        }
    }
}

// ========== prep: all weight transposes/converts in ONE launch ==============
// grid (16,16,12): z 0-2 = wq/wk/wv (bf16 hi/lo), z 3 = wo (fp16),
// z 4-7 = w1 (fp16), z 8-11 = w2 (fp16).
__global__ void __launch_bounds__(256) prep_weights(
    const float* __restrict__ wq, const float* __restrict__ wk,
    const float* __restrict__ wv, const float* __restrict__ wo,
    const float* __restrict__ w1, const float* __restrict__ w2,
    __nv_bfloat16* __restrict__ wqkvh, __nv_bfloat16* __restrict__ wqkvl,
    __half* __restrict__ wof,
    __half* __restrict__ w1f, __half* __restrict__ w2f)
{
    __shared__ float t[32][33];
    int z = blockIdx.z;
    int tx = threadIdx.x & 31, ty = threadIdx.x >> 5;

    const float* w; int Nd; size_t kbase = 0, nbase = 0;
    if (z < 3)      { w = (z == 0) ? wq : (z == 1) ? wk : wv; Nd = DD; }
    else if (z == 3){ w = wo; Nd = DD; }
    else if (z < 8) { w = w1; Nd = DFF; nbase = (size_t)(z - 4) * 512; }
    else            { w = w2; Nd = DD;  kbase = (size_t)(z - 8) * 512; }

    size_t k0 = kbase + blockIdx.x * 32;
    size_t n0 = nbase + blockIdx.y * 32;

    #pragma unroll
    for (int i = 0; i < 4; i++)
        t[ty + 8 * i][tx] = w[(k0 + ty + 8 * i) * Nd + n0 + tx];
    __syncthreads();
    #pragma unroll
    for (int i = 0; i < 4; i++) {
        float v = t[tx][ty + 8 * i];
        size_t nout = n0 + ty + 8 * i;
        size_t kout = k0 + tx;
        if (z < 3) {
            __nv_bfloat16 h = __float2bfloat16(v);
            __nv_bfloat16 l = __float2bfloat16(v - __bfloat162float(h));
            size_t o = ((size_t)z * DD + nout) * DD + kout;
            wqkvh[o] = h; wqkvl[o] = l;
        } else if (z == 3) {
            wof[nout * DD + kout] = __float2half_rn(v);
        } else if (z < 8) {
            w1f[nout * DD + kout] = __float2half_rn(v);    // [2048][512]
        } else {
            w2f[nout * DFF + kout] = __float2half_rn(v);   // [512][2048]
        }
    }
}

// ---------------- LayerNorm -> bf16 hi/lo ------------------------------------
__global__ void __launch_bounds__(256) ln_kernel(
    const float* __restrict__ x, const float* __restrict__ g,
    const float* __restrict__ be, __nv_bfloat16* __restrict__ oh,
    __nv_bfloat16* __restrict__ ol)
{
    int row = blockIdx.x;
    const float* xr = x + (size_t)row * DD;
    int t = threadIdx.x;
    float v0 = xr[t], v1 = xr[t + 256];
    float s = v0 + v1, ss = v0 * v0 + v1 * v1;
    #pragma unroll
    for (int o = 16; o; o >>= 1) {
        s  += __shfl_xor_sync(0xFFFFFFFFu, s,  o);
        ss += __shfl_xor_sync(0xFFFFFFFFu, ss, o);
    }
    __shared__ float red0[8], red1[8];
    __shared__ float smean, srstd;
    int wid = t >> 5, lane = t & 31;
    if (lane == 0) { red0[wid] = s; red1[wid] = ss; }
    __syncthreads();
    if (t == 0) {
        float a = 0.f, b2 = 0.f;
        #pragma unroll
        for (int i = 0; i < 8; i++) { a += red0[i]; b2 += red1[i]; }
        float mean = a * (1.0f / DD);
        float var  = b2 * (1.0f / DD) - mean * mean;
        smean = mean;
        srstd = rsqrtf(var + 1e-5f);
    }
    __syncthreads();
    float m = smean, r = srstd;
    float y0 = (v0 - m) * r * g[t]       + be[t];
    float y1 = (v1 - m) * r * g[t + 256] + be[t + 256];
    __nv_bfloat16 h0 = __float2bfloat16(y0);
    __nv_bfloat16 h1 = __float2bfloat16(y1);
    size_t o0 = (size_t)row * DD + t;
    oh[o0]       = h0;
    oh[o0 + 256] = h1;
    ol[o0]       = __float2bfloat16(y0 - __bfloat162float(h0));
    ol[o0 + 256] = __float2bfloat16(y1 - __bfloat162float(h1));
}

// ---------------- LayerNorm -> fp16 (for FFN) --------------------------------
__global__ void __launch_bounds__(256) ln_fp16(
    const float* __restrict__ x, const float* __restrict__ g,
    const float* __restrict__ be, __half* __restrict__ out)
{
    int row = blockIdx.x;
    const float* xr = x + (size_t)row * DD;
    int t = threadIdx.x;
    float v0 = xr[t], v1 = xr[t + 256];
    float s = v0 + v1, ss = v0 * v0 + v1 * v1;
    #pragma unroll
    for (int o = 16; o; o >>= 1) {
        s  += __shfl_xor_sync(0xFFFFFFFFu, s,  o);
        ss += __shfl_xor_sync(0xFFFFFFFFu, ss, o);
    }
    __shared__ float red0[8], red1[8];
    __shared__ float smean, srstd;
    int wid = t >> 5, lane = t & 31;
    if (lane == 0) { red0[wid] = s; red1[wid] = ss; }
    __syncthreads();
    if (t == 0) {
        float a = 0.f, b2 = 0.f;
        #pragma unroll
        for (int i = 0; i < 8; i++) { a += red0[i]; b2 += red1[i]; }
        float mean = a * (1.0f / DD);
        float var  = b2 * (1.0f / DD) - mean * mean;
        smean = mean;
        srstd = rsqrtf(var + 1e-5f);
    }
    __syncthreads();
    float m = smean, r = srstd;
    out[(size_t)row * DD + t]       = __float2half_rn((v0 - m) * r * g[t]       + be[t]);
    out[(size_t)row * DD + t + 256] = __float2half_rn((v1 - m) * r * g[t + 256] + be[t + 256]);
}

// ---------------- top-16 + softmax + sparse A*V -> fp16 ---------------------
__global__ void __launch_bounds__(256) topk_kernel(
    const float* __restrict__ logits, const float* __restrict__ v,
    __half* __restrict__ attn)
{
    int w = (blockIdx.x * blockDim.x + threadIdx.x) >> 5;
    int lane = threadIdx.x & 31;
    int n = w & (NN - 1);
    int h = (w >> 9) & 7;
    int b = w >> 12;

    const float* lrow = logits + (size_t)w * NN;
    float vals[16];
    #pragma unroll
    for (int t = 0; t < 16; t++) vals[t] = lrow[t * 32 + lane];

    unsigned mask = 0xFFFFu;
    float selv = 0.f;
    int   selm = 0;
    #pragma unroll
    for (int r = 0; r < 16; r++) {
        float bv = -INFINITY; int bs = 0;
        #pragma unroll
        for (int t = 0; t < 16; t++) {
            bool live = (mask >> t) & 1u;
            if (live && vals[t] > bv) { bv = vals[t]; bs = t; }
        }
        float rv = bv;
        int rm = bs * 32 + lane;
        #pragma unroll
        for (int off = 16; off; off >>= 1) {
            float ov = __shfl_xor_sync(0xFFFFFFFFu, rv, off);
            int   om = __shfl_xor_sync(0xFFFFFFFFu, rm, off);
            if (ov > rv || (ov == rv && om < rm)) { rv = ov; rm = om; }
        }
        if ((rm & 31) == lane) mask &= ~(1u << (rm >> 5));
        if (lane == r) { selv = rv; selm = rm; }
    }

    float maxv = __shfl_sync(0xFFFFFFFFu, selv, 0);
    float e = (lane < 16) ? expf(selv - maxv) : 0.f;
    float s = e;
    #pragma unroll
    for (int off = 16; off; off >>= 1) s += __shfl_xor_sync(0xFFFFFFFFu, s, off);
    float p = e / s;

    float o0 = 0.f, o1 = 0.f;
    const float* vbase = v + ((size_t)b * NN) * DD + h * HD;
    #pragma unroll
    for (int l = 0; l < 16; l++) {
        float pl = __shfl_sync(0xFFFFFFFFu, p, l);
        int   ml = __shfl_sync(0xFFFFFFFFu, selm, l);
        const float* vr = vbase + (size_t)ml * DD;
        o0 += pl * vr[lane];
        o1 += pl * vr[lane + 32];
    }
    size_t base = ((size_t)(b * NN + n)) * DD + h * HD;
    attn[base + lane]      = __float2half_rn(o0);
    attn[base + lane + 32] = __float2half_rn(o1);
}

// ---------------------------------------------------------------------------
extern "C" void kernel_launch(void* const* d_in, const int* in_sizes, int n_in,
                              void* d_out, int out_size)
{
    const float* x   = (const float*)d_in[0];
    const float* wq  = (const float*)d_in[1];
    const float* bq  = (const float*)d_in[2];
    const float* wk  = (const float*)d_in[3];
    const float* bk  = (const float*)d_in[4];
    const float* wv  = (const float*)d_in[5];
    const float* bv  = (const float*)d_in[6];
    const float* wo  = (const float*)d_in[7];
    const float* bo  = (const float*)d_in[8];
    const float* g1  = (const float*)d_in[9];
    const float* be1 = (const float*)d_in[10];
    const float* g2  = (const float*)d_in[11];
    const float* be2 = (const float*)d_in[12];
    const float* w1  = (const float*)d_in[13];
    const float* bf1 = (const float*)d_in[14];
    const float* w2  = (const float*)d_in[15];
    const float* bf2 = (const float*)d_in[16];
    const float* rel = (const float*)d_in[17];
    float* out = (float*)d_out;

    float *v, *logits, *x1;
    __nv_bfloat16 *qh, *ql, *kh, *kl, *xnh, *xnl, *wqkvh, *wqkvl;
    __half *attnf, *wof, *xn2f, *fff, *w1f, *w2f;
    cudaGetSymbolAddress((void**)&v,      g_v);
    cudaGetSymbolAddress((void**)&logits, g_logits);
    cudaGetSymbolAddress((void**)&x1,     g_x1);
    cudaGetSymbolAddress((void**)&qh,     g_qb_h);
    cudaGetSymbolAddress((void**)&ql,     g_qb_l);
    cudaGetSymbolAddress((void**)&kh,     g_kb_h);
    cudaGetSymbolAddress((void**)&kl,     g_kb_l);
    cudaGetSymbolAddress((void**)&xnh,    g_xnb_h);
    cudaGetSymbolAddress((void**)&xnl,    g_xnb_l);
    cudaGetSymbolAddress((void**)&wqkvh,  g_wqkv_h);
    cudaGetSymbolAddress((void**)&wqkvl,  g_wqkv_l);
    cudaGetSymbolAddress((void**)&attnf,  g_attnf);
    cudaGetSymbolAddress((void**)&wof,    g_wof);
    cudaGetSymbolAddress((void**)&xn2f,   g_xn2f);
    cudaGetSymbolAddress((void**)&fff,    g_fff);
    cudaGetSymbolAddress((void**)&w1f,    g_w1f);
    cudaGetSymbolAddress((void**)&w2f,    g_w2f);

    const int SMEM_GEMM = 2 * BUFB;   // 81920
    const int SMEM_FP16 = 2 * BUF2;   // 40960
    cudaFuncSetAttribute(gemm_qkv,     cudaFuncAttributeMaxDynamicSharedMemorySize, SMEM_GEMM);
    cudaFuncSetAttribute(logits_mma,   cudaFuncAttributeMaxDynamicSharedMemorySize, SMEM_GEMM);
    cudaFuncSetAttribute(gemm_fp16<0>, cudaFuncAttributeMaxDynamicSharedMemorySize, SMEM_FP16);
    cudaFuncSetAttribute(gemm_fp16<1>, cudaFuncAttributeMaxDynamicSharedMemorySize, SMEM_FP16);

    dim3 gD(DD / 128, ROWS / 128);       // 4 x 64
    dim3 gQKV(3 * DD / 128, ROWS / 128); // 12 x 64
    dim3 gF(DFF / 128, ROWS / 128);      // 16 x 64

    // 1. all weight converts in one launch
    prep_weights<<<dim3(16, 16, 12), 256>>>(wq, wk, wv, wo, w1, w2,
                                            wqkvh, wqkvl, wof, w1f, w2f);
    // 2. LN1 -> bf16 hi/lo
    ln_kernel<<<ROWS, 256>>>(x, g1, be1, xnh, xnl);
    // 3. fused QKV projection (Q,K bf16x3; V single)
    gemm_qkv<<<gQKV, 256, SMEM_GEMM>>>(xnh, xnl, wqkvh, wqkvl,
                                       bq, bk, bv, qh, ql, kh, kl, v);
    // 4. logits + relative bias (bf16x3)
    logits_mma<<<dim3(NN / 128, NN / 128, BB * HH), 256, SMEM_GEMM>>>(qh, ql, kh, kl, rel, logits);
    // 5. top-16 -> softmax -> sparse A*V -> fp16
    topk_kernel<<<(BB * HH * NN * 32) / 256, 256>>>(logits, v, attnf);
    // 6. output projection + residual (fp16 x1)
    gemm_fp16<1><<<gD, 256, SMEM_FP16>>>(attnf, wof, bo, x, x1, DD, DD);
    // 7. LN2 -> fp16
    ln_fp16<<<ROWS, 256>>>(x1, g2, be2, xn2f);
    // 8. FFN up + exact GELU (fp16 x1) -> fp16
    gemm_fp16<0><<<gF, 256, SMEM_FP16>>>(xn2f, w1f, bf1, nullptr, fff, DFF, DD);
    // 9. FFN down + residual (fp16 x1) -> output
    gemm_fp16<1><<<gD, 256, SMEM_FP16>>>(fff, w2f, bf2, x1, out, DD, DFF);
}

// round 13
// speedup vs baseline: 1.4970x; 1.0286x over previous
#include <cuda_runtime.h>
#include <cuda_bf16.h>
#include <cuda_fp16.h>
#include <math.h>
#include <stdint.h>

#define BB   16
#define NN   512
#define DD   512
#define HH   8
#define KTOP 16
#define HD   64
#define MSL  512
#define ROWS (BB*NN)     // 8192
#define DFF  2048
#define GRPB 8           // batches per logits/topk group (L2-resident)

// ---------------- scratch (static device memory; no allocs allowed) ----------
__device__ float g_logits[(size_t)GRPB*HH*NN*NN];   // 67 MB (L2-resident group)
__device__ float g_x1   [ROWS*DD];

__device__ __nv_bfloat16 g_qb_h  [ROWS*DD];
__device__ __nv_bfloat16 g_qb_l  [ROWS*DD];
__device__ __nv_bfloat16 g_kb_h  [ROWS*DD];
__device__ __nv_bfloat16 g_kb_l  [ROWS*DD];
__device__ __nv_bfloat16 g_xnb_h  [ROWS*DD];
__device__ __nv_bfloat16 g_xnb_l  [ROWS*DD];
__device__ __nv_bfloat16 g_wqkv_h [3*DD*DD];      // packed Q|K|V, [1536][512]
__device__ __nv_bfloat16 g_wqkv_l [3*DD*DD];

__device__ __half g_vf   [ROWS*DD];               // V (fp16)
__device__ __half g_attnf[ROWS*DD];               // attn out (fp16)
__device__ __half g_wof  [DD*DD];                 // wo^T fp16
__device__ __half g_xn2f [ROWS*DD];               // LN2 out (fp16)
__device__ __half g_fff  [(size_t)ROWS*DFF];      // FFN hidden (fp16)
__device__ __half g_w1f  [(size_t)DD*DFF];        // w1^T fp16 [2048][512]
__device__ __half g_w2f  [(size_t)DFF*DD];        // w2^T fp16 [512][2048]

// ================= PTX helpers (base sm_103 target legal) ====================
__device__ __forceinline__ uint32_t smem_u32(const void* p) {
    uint32_t a;
    asm("{ .reg .u64 t; cvta.to.shared.u64 t, %1; cvt.u32.u64 %0, t; }" : "=r"(a) : "l"(p));
    return a;
}
__device__ __forceinline__ void cpa16(uint32_t dst, const void* src) {
    asm volatile("cp.async.cg.shared.global [%0], [%1], 16;" :: "r"(dst), "l"(src));
}
__device__ __forceinline__ void cpa_commit() {
    asm volatile("cp.async.commit_group;" ::: "memory");
}
template<int N>
__device__ __forceinline__ void cpa_wait() {
    asm volatile("cp.async.wait_group %0;" :: "n"(N) : "memory");
}
__device__ __forceinline__ void ldsm4(uint32_t* r, uint32_t addr) {
    asm volatile("ldmatrix.sync.aligned.m8n8.x4.shared.b16 {%0,%1,%2,%3}, [%4];"
                 : "=r"(r[0]), "=r"(r[1]), "=r"(r[2]), "=r"(r[3]) : "r"(addr));
}
__device__ __forceinline__ void mma16816(float* c, const uint32_t* a, const uint32_t* b) {
    asm volatile(
        "mma.sync.aligned.m16n8k16.row.col.f32.bf16.bf16.f32 "
        "{%0,%1,%2,%3}, {%4,%5,%6,%7}, {%8,%9}, {%0,%1,%2,%3};"
        : "+f"(c[0]), "+f"(c[1]), "+f"(c[2]), "+f"(c[3])
        : "r"(a[0]), "r"(a[1]), "r"(a[2]), "r"(a[3]), "r"(b[0]), "r"(b[1]));
}
__device__ __forceinline__ void mma16816h(float* c, const uint32_t* a, const uint32_t* b) {
    asm volatile(
        "mma.sync.aligned.m16n8k16.row.col.f32.f16.f16.f32 "
        "{%0,%1,%2,%3}, {%4,%5,%6,%7}, {%8,%9}, {%0,%1,%2,%3};"
        : "+f"(c[0]), "+f"(c[1]), "+f"(c[2]), "+f"(c[3])
        : "r"(a[0]), "r"(a[1]), "r"(a[2]), "r"(a[3]), "r"(b[0]), "r"(b[1]));
}

#define LDA 40                         // padded smem row (elements)
#define TILEB (128 * LDA * 2)          // 10240 bytes per tile
#define BUFB  (4 * TILEB)              // Ah,Al,Bh,Bl per buffer (bf16x3)
#define BUF2  (2 * TILEB)              // A,B per buffer (fp16)

// ======= shared mainloop: bf16 mma over K, double-buffered, 1 sync/step =====
// order: [wait stage s][sync][prefetch s+1][mma s]  (post-mma barrier elided:
// the single barrier proves all warps finished mma s-1, making the s+1 write
// into buf^1 -- last read by mma s-1 -- WAR-safe)
#define GEMM_CORE(APH, APL, BPH, BPL, STRIDE, SCOUNT, TRIPLE)                  \
    int r0 = tid >> 2, c0 = (tid & 3) * 8;                                     \
    int r1 = r0 + 64;                                                          \
    uint32_t off0 = (uint32_t)(r0 * LDA + c0) * 2;                             \
    uint32_t off1 = (uint32_t)(r1 * LDA + c0) * 2;                             \
    auto load_stage = [&](int s, int buf) {                                    \
        int k0 = s * 32;                                                       \
        uint32_t b = sbase + buf * BUFB;                                       \
        cpa16(b             + off0, APH + (size_t)r0 * STRIDE + k0 + c0);      \
        cpa16(b             + off1, APH + (size_t)r1 * STRIDE + k0 + c0);      \
        cpa16(b + 2 * TILEB + off0, BPH + (size_t)r0 * STRIDE + k0 + c0);      \
        cpa16(b + 2 * TILEB + off1, BPH + (size_t)r1 * STRIDE + k0 + c0);      \
        if (TRIPLE) {                                                          \
            cpa16(b + TILEB     + off0, APL + (size_t)r0 * STRIDE + k0 + c0);  \
            cpa16(b + TILEB     + off1, APL + (size_t)r1 * STRIDE + k0 + c0);  \
            cpa16(b + 3 * TILEB + off0, BPL + (size_t)r0 * STRIDE + k0 + c0);  \
            cpa16(b + 3 * TILEB + off1, BPL + (size_t)r1 * STRIDE + k0 + c0);  \
        }                                                                      \
    };                                                                         \
    load_stage(0, 0);                                                          \
    cpa_commit();                                                              \
    uint32_t a_off[2], b_off[4];                                               \
    _Pragma("unroll")                                                          \
    for (int mt = 0; mt < 2; mt++) {                                           \
        int row = wr * 32 + mt * 16 + (lane & 15);                             \
        a_off[mt] = (uint32_t)(row * LDA + (lane >> 4) * 8) * 2;               \
    }                                                                          \
    _Pragma("unroll")                                                          \
    for (int nt = 0; nt < 4; nt++) {                                           \
        int nrow = wc * 64 + nt * 16 + (lane & 7) + ((lane >> 4) & 1) * 8;     \
        b_off[nt] = (uint32_t)(nrow * LDA + ((lane >> 3) & 1) * 8) * 2;        \
    }                                                                          \
    for (int s = 0; s < SCOUNT; s++) {                                         \
        int buf = s & 1;                                                       \
        cpa_wait<0>();                                                         \
        __syncthreads();                                                       \
        if (s + 1 < SCOUNT) { load_stage(s + 1, buf ^ 1); cpa_commit(); }      \
        uint32_t ah = sbase + buf * BUFB;                                      \
        uint32_t al = ah + TILEB;                                              \
        uint32_t bh = ah + 2 * TILEB;                                          \
        uint32_t bl = ah + 3 * TILEB;                                          \
        _Pragma("unroll")                                                      \
        for (int kk = 0; kk < 2; kk++) {                                       \
            uint32_t afh[2][4], afl[2][4];                                     \
            _Pragma("unroll")                                                  \
            for (int mt = 0; mt < 2; mt++) {                                   \
                ldsm4(afh[mt], ah + a_off[mt] + kk * 32);                      \
                if (TRIPLE) ldsm4(afl[mt], al + a_off[mt] + kk * 32);          \
            }                                                                  \
            _Pragma("unroll")                                                  \
            for (int nt = 0; nt < 4; nt++) {                                   \
                uint32_t bfh[4], bfl[4];                                       \
                ldsm4(bfh, bh + b_off[nt] + kk * 32);                          \
                if (TRIPLE) ldsm4(bfl, bl + b_off[nt] + kk * 32);              \
                _Pragma("unroll")                                              \
                for (int mt = 0; mt < 2; mt++) {                               \
                    mma16816(acc[mt][nt * 2 + 0], afh[mt], bfh + 0);           \
                    mma16816(acc[mt][nt * 2 + 1], afh[mt], bfh + 2);           \
                    if (TRIPLE) {                                              \
                        mma16816(acc[mt][nt * 2 + 0], afl[mt], bfh + 0);       \
                        mma16816(acc[mt][nt * 2 + 1], afl[mt], bfh + 2);       \
                        mma16816(acc[mt][nt * 2 + 0], afh[mt], bfl + 0);       \
                        mma16816(acc[mt][nt * 2 + 1], afh[mt], bfl + 2);       \
                    }                                                          \
                }                                                              \
            }                                                                  \
        }                                                                      \
    }                                                                          \
    __syncthreads();

#define ACC_INIT                                                               \
    float acc[2][8][4];                                                        \
    _Pragma("unroll")                                                          \
    for (int i = 0; i < 2; i++)                                                \
        _Pragma("unroll")                                                      \
        for (int j = 0; j < 8; j++)                                            \
            _Pragma("unroll")                                                  \
            for (int q = 0; q < 4; q++) acc[i][j][q] = 0.f;

// ================= fused QKV GEMM: N=1536 packed, mixed epilogue ============
// Q,K blocks: bf16x3 (selection-critical). V blocks: single bf16 mma -> fp16.
__global__ void __launch_bounds__(256, 2) gemm_qkv(
    const __nv_bfloat16* __restrict__ Ah, const __nv_bfloat16* __restrict__ Al,
    const __nv_bfloat16* __restrict__ Bh, const __nv_bfloat16* __restrict__ Bl,
    const float* __restrict__ bq, const float* __restrict__ bk,
    const float* __restrict__ bv,
    __nv_bfloat16* __restrict__ qh, __nv_bfloat16* __restrict__ ql,
    __nv_bfloat16* __restrict__ kh, __nv_bfloat16* __restrict__ kl,
    __half* __restrict__ vf)
{
    extern __shared__ char smem[];
    uint32_t sbase = smem_u32(smem);
    int tid = threadIdx.x, wid = tid >> 5, lane = tid & 31;
    int n0 = blockIdx.x * 128, m0 = blockIdx.y * 128;
    int wr = wid & 3, wc = wid >> 2;
    bool triple = (n0 < 1024);           // Q,K need hi/lo; V single

    const __nv_bfloat16* Aph = Ah + (size_t)m0 * DD;
    const __nv_bfloat16* Apl = Al + (size_t)m0 * DD;
    const __nv_bfloat16* Bph = Bh + (size_t)n0 * DD;
    const __nv_bfloat16* Bpl = Bl + (size_t)n0 * DD;

    ACC_INIT;
    GEMM_CORE(Aph, Apl, Bph, Bpl, DD, 16, triple);

    int gr = lane >> 2, tg = lane & 3;
    int sel = n0 >> 9;                       // 0=Q, 1=K, 2=V
    const float* bias = (sel == 0) ? bq : (sel == 1) ? bk : bv;
    __nv_bfloat16* oh = (sel == 0) ? qh : kh;
    __nv_bfloat16* ol = (sel == 0) ? ql : kl;
    int nloc = n0 & 511;
    #pragma unroll
    for (int mt = 0; mt < 2; mt++) {
        int rbase = m0 + wr * 32 + mt * 16 + gr;
        #pragma unroll
        for (int j = 0; j < 8; j++) {
            int col = nloc + wc * 64 + j * 8 + tg * 2;
            #pragma unroll
            for (int half2_ = 0; half2_ < 2; half2_++) {
                int row = rbase + half2_ * 8;
                float v0 = acc[mt][j][half2_ * 2 + 0] + bias[col];
                float v1 = acc[mt][j][half2_ * 2 + 1] + bias[col + 1];
                if (sel == 2) {
                    __half2 p;
                    p.x = __float2half_rn(v0);
                    p.y = __float2half_rn(v1);
                    *(__half2*)(vf + (size_t)row * DD + col) = p;
                } else {
                    __nv_bfloat162 ph, pl;
                    ph.x = __float2bfloat16(v0);
                    ph.y = __float2bfloat16(v1);
                    pl.x = __float2bfloat16(v0 - __bfloat162float(ph.x));
                    pl.y = __float2bfloat16(v1 - __bfloat162float(ph.y));
                    *(__nv_bfloat162*)(oh + (size_t)row * DD + col) = ph;
                    *(__nv_bfloat162*)(ol + (size_t)row * DD + col) = pl;
                }
            }
        }
    }
}

// ============ logits: bf16x3 HMMA, per (b,h), 128x128 tile, Kd=64 ===========
// Writes into the GROUP-LOCAL logits buffer (GRPB batches).
__global__ void __launch_bounds__(256, 2) logits_mma(
    const __nv_bfloat16* __restrict__ Qh, const __nv_bfloat16* __restrict__ Ql,
    const __nv_bfloat16* __restrict__ Kh, const __nv_bfloat16* __restrict__ Kl,
    const float* __restrict__ rel, float* __restrict__ logits, int bbase)
{
    extern __shared__ char smem[];
    uint32_t sbase = smem_u32(smem);
    int tid = threadIdx.x, wid = tid >> 5, lane = tid & 31;
    int bh2 = blockIdx.z;                 // local (b,h) within group
    int b = bbase + (bh2 >> 3), h = bh2 & 7;
    int n0 = blockIdx.x * 128;
    int m0 = blockIdx.y * 128;
    int wr = wid & 3, wc = wid >> 2;

    const __nv_bfloat16* Aph = Qh + ((size_t)(b * NN + m0)) * DD + h * HD;
    const __nv_bfloat16* Apl = Ql + ((size_t)(b * NN + m0)) * DD + h * HD;
    const __nv_bfloat16* Bph = Kh + ((size_t)(b * NN + n0)) * DD + h * HD;
    const __nv_bfloat16* Bpl = Kl + ((size_t)(b * NN + n0)) * DD + h * HD;

    ACC_INIT;
    GEMM_CORE(Aph, Apl, Bph, Bpl, DD, 2, true);

    float* lbase = logits + (size_t)bh2 * NN * NN;    // group-local
    int gr = lane >> 2, tg = lane & 3;
    #pragma unroll
    for (int mt = 0; mt < 2; mt++) {
        int rbase = m0 + wr * 32 + mt * 16 + gr;
        #pragma unroll
        for (int j = 0; j < 8; j++) {
            int col = n0 + wc * 64 + j * 8 + tg * 2;
            #pragma unroll
            for (int half2_ = 0; half2_ < 2; half2_++) {
                int row = rbase + half2_ * 8;
                float2 o;
                o.x = acc[mt][j][half2_ * 2 + 0] * 0.125f + rel[(col + 0 - row + MSL - 1) * HH + h];
                o.y = acc[mt][j][half2_ * 2 + 1] * 0.125f + rel[(col + 1 - row + MSL - 1) * HH + h];
                *(float2*)(lbase + (size_t)row * NN + col) = o;
            }
        }
    }
}

// ================= fp16 single-mma GEMM, 128x128 tile =======================
// MODE 0: half = gelu(acc + bias)    MODE 1: fp32 = acc + bias + res
template<int MODE>
__global__ void __launch_bounds__(256, 2) gemm_fp16(
    const __half* __restrict__ A, const __half* __restrict__ Bt,
    const float* __restrict__ bias, const float* __restrict__ res,
    void* __restrict__ Cout, int N, int Kd)
{
    extern __shared__ char smem[];
    uint32_t sbase = smem_u32(smem);
    int tid = threadIdx.x, wid = tid >> 5, lane = tid & 31;
    int n0 = blockIdx.x * 128, m0 = blockIdx.y * 128;
    int wr = wid & 3, wc = wid >> 2;

    const __half* Ap = A + (size_t)m0 * Kd;
    const __half* Bp = Bt + (size_t)n0 * Kd;

    ACC_INIT;

    int r0 = tid >> 2, c0 = (tid & 3) * 8;
    int r1 = r0 + 64;
    uint32_t off0 = (uint32_t)(r0 * LDA + c0) * 2;
    uint32_t off1 = (uint32_t)(r1 * LDA + c0) * 2;
    auto load_stage = [&](int s, int buf) {
        int k0 = s * 32;
        uint32_t b = sbase + buf * BUF2;
        cpa16(b         + off0, Ap + (size_t)r0 * Kd + k0 + c0);
        cpa16(b         + off1, Ap + (size_t)r1 * Kd + k0 + c0);
        cpa16(b + TILEB + off0, Bp + (size_t)r0 * Kd + k0 + c0);
        cpa16(b + TILEB + off1, Bp + (size_t)r1 * Kd + k0 + c0);
    };
    int S = Kd >> 5;
    load_stage(0, 0);
    cpa_commit();

    uint32_t a_off[2], b_off[4];
    #pragma unroll
    for (int mt = 0; mt < 2; mt++) {
        int row = wr * 32 + mt * 16 + (lane & 15);
        a_off[mt] = (uint32_t)(row * LDA + (lane >> 4) * 8) * 2;
    }
    #pragma unroll
    for (int nt = 0; nt < 4; nt++) {
        int nrow = wc * 64 + nt * 16 + (lane & 7) + ((lane >> 4) & 1) * 8;
        b_off[nt] = (uint32_t)(nrow * LDA + ((lane >> 3) & 1) * 8) * 2;
    }

    for (int s = 0; s < S; s++) {
        int buf = s & 1;
        cpa_wait<0>();
        __syncthreads();
        if (s + 1 < S) { load_stage(s + 1, buf ^ 1); cpa_commit(); }

        uint32_t ab = sbase + buf * BUF2;
        uint32_t bb = ab + TILEB;
        #pragma unroll
        for (int kk = 0; kk < 2; kk++) {
            uint32_t af[2][4];
            #pragma unroll
            for (int mt = 0; mt < 2; mt++) ldsm4(af[mt], ab + a_off[mt] + kk * 32);
            #pragma unroll
            for (int nt = 0; nt < 4; nt++) {
                uint32_t bf[4];
                ldsm4(bf, bb + b_off[nt] + kk * 32);
                #pragma unroll
                for (int mt = 0; mt < 2; mt++) {
                    mma16816h(acc[mt][nt * 2 + 0], af[mt], bf + 0);
                    mma16816h(acc[mt][nt * 2 + 1], af[mt], bf + 2);
                }
            }
        }
    }

    int gr = lane >> 2, tg = lane & 3;
    #pragma unroll
    for (int mt = 0; mt < 2; mt++) {
        int rbase = m0 + wr * 32 + mt * 16 + gr;
        #pragma unroll
        for (int j = 0; j < 8; j++) {
            int col = n0 + wc * 64 + j * 8 + tg * 2;
            #pragma unroll
            for (int half2_ = 0; half2_ < 2; half2_++) {
                int row = rbase + half2_ * 8;
                float v0 = acc[mt][j][half2_ * 2 + 0] + bias[col];
                float v1 = acc[mt][j][half2_ * 2 + 1] + bias[col + 1];
                if (MODE == 0) {
                    v0 = 0.5f * v0 * (1.0f + erff(v0 * 0.70710678118654752f));
                    v1 = 0.5f * v1 * (1.0f + erff(v1 * 0.70710678118654752f));
                    __half2 p;
                    p.x = __float2half_rn(v0);
                    p.y = __float2half_rn(v1);
                    *(__half2*)((__half*)Cout + (size_t)row * N + col) = p;
                } else {
                    const float* rr = res + (size_t)row * N + col;
                    float2 o; o.x = v0 + rr[0]; o.y = v1 + rr[1];
                    *(float2*)((float*)Cout + (size_t)row * N + col) = o;
                }
            }
        }
    }
}

// ========== prep: all weight transposes/converts in ONE launch ==============
__global__ void __launch_bounds__(256) prep_weights(
    const float* __restrict__ wq, const float* __restrict__ wk,
    const float* __restrict__ wv, const float* __restrict__ wo,
    const float* __restrict__ w1, const float* __restrict__ w2,
    __nv_bfloat16* __restrict__ wqkvh, __nv_bfloat16* __restrict__ wqkvl,
    __half* __restrict__ wof,
    __half* __restrict__ w1f, __half* __restrict__ w2f)
{
    __shared__ float t[32][33];
    int z = blockIdx.z;
    int tx = threadIdx.x & 31, ty = threadIdx.x >> 5;

    const float* w; int Nd; size_t kbase = 0, nbase = 0;
    if (z < 3)      { w = (z == 0) ? wq : (z == 1) ? wk : wv; Nd = DD; }
    else if (z == 3){ w = wo; Nd = DD; }
    else if (z < 8) { w = w1; Nd = DFF; nbase = (size_t)(z - 4) * 512; }
    else            { w = w2; Nd = DD;  kbase = (size_t)(z - 8) * 512; }

    size_t k0 = kbase + blockIdx.x * 32;
    size_t n0 = nbase + blockIdx.y * 32;

    #pragma unroll
    for (int i = 0; i < 4; i++)
        t[ty + 8 * i][tx] = w[(k0 + ty + 8 * i) * Nd + n0 + tx];
    __syncthreads();
    #pragma unroll
    for (int i = 0; i < 4; i++) {
        float v = t[tx][ty + 8 * i];
        size_t nout = n0 + ty + 8 * i;
        size_t kout = k0 + tx;
        if (z < 3) {
            __nv_bfloat16 h = __float2bfloat16(v);
            __nv_bfloat16 l = __float2bfloat16(v - __bfloat162float(h));
            size_t o = ((size_t)z * DD + nout) * DD + kout;
            wqkvh[o] = h; wqkvl[o] = l;
        } else if (z == 3) {
            wof[nout * DD + kout] = __float2half_rn(v);
        } else if (z < 8) {
            w1f[nout * DD + kout] = __float2half_rn(v);    // [2048][512]
        } else {
            w2f[nout * DFF + kout] = __float2half_rn(v);   // [512][2048]
        }
    }
}

// ---------------- LayerNorm -> bf16 hi/lo ------------------------------------
__global__ void __launch_bounds__(256) ln_kernel(
    const float* __restrict__ x, const float* __restrict__ g,
    const float* __restrict__ be, __nv_bfloat16* __restrict__ oh,
    __nv_bfloat16* __restrict__ ol)
{
    int row = blockIdx.x;
    const float* xr = x + (size_t)row * DD;
    int t = threadIdx.x;
    float v0 = xr[t], v1 = xr[t + 256];
    float s = v0 + v1, ss = v0 * v0 + v1 * v1;
    #pragma unroll
    for (int o = 16; o; o >>= 1) {
        s  += __shfl_xor_sync(0xFFFFFFFFu, s,  o);
        ss += __shfl_xor_sync(0xFFFFFFFFu, ss, o);
    }
    __shared__ float red0[8], red1[8];
    __shared__ float smean, srstd;
    int wid = t >> 5, lane = t & 31;
    if (lane == 0) { red0[wid] = s; red1[wid] = ss; }
    __syncthreads();
    if (t == 0) {
        float a = 0.f, b2 = 0.f;
        #pragma unroll
        for (int i = 0; i < 8; i++) { a += red0[i]; b2 += red1[i]; }
        float mean = a * (1.0f / DD);
        float var  = b2 * (1.0f / DD) - mean * mean;
        smean = mean;
        srstd = rsqrtf(var + 1e-5f);
    }
    __syncthreads();
    float m = smean, r = srstd;
    float y0 = (v0 - m) * r * g[t]       + be[t];
    float y1 = (v1 - m) * r * g[t + 256] + be[t + 256];
    __nv_bfloat16 h0 = __float2bfloat16(y0);
    __nv_bfloat16 h1 = __float2bfloat16(y1);
    size_t o0 = (size_t)row * DD + t;
    oh[o0]       = h0;
    oh[o0 + 256] = h1;
    ol[o0]       = __float2bfloat16(y0 - __bfloat162float(h0));
    ol[o0 + 256] = __float2bfloat16(y1 - __bfloat162float(h1));
}

// ---------------- LayerNorm -> fp16 (for FFN) --------------------------------
__global__ void __launch_bounds__(256) ln_fp16(
    const float* __restrict__ x, const float* __restrict__ g,
    const float* __restrict__ be, __half* __restrict__ out)
{
    int row = blockIdx.x;
    const float* xr = x + (size_t)row * DD;
    int t = threadIdx.x;
    float v0 = xr[t], v1 = xr[t + 256];
    float s = v0 + v1, ss = v0 * v0 + v1 * v1;
    #pragma unroll
    for (int o = 16; o; o >>= 1) {
        s  += __shfl_xor_sync(0xFFFFFFFFu, s,  o);
        ss += __shfl_xor_sync(0xFFFFFFFFu, ss, o);
    }
    __shared__ float red0[8], red1[8];
    __shared__ float smean, srstd;
    int wid = t >> 5, lane = t & 31;
    if (lane == 0) { red0[wid] = s; red1[wid] = ss; }
    __syncthreads();
    if (t == 0) {
        float a = 0.f, b2 = 0.f;
        #pragma unroll
        for (int i = 0; i < 8; i++) { a += red0[i]; b2 += red1[i]; }
        float mean = a * (1.0f / DD);
        float var  = b2 * (1.0f / DD) - mean * mean;
        smean = mean;
        srstd = rsqrtf(var + 1e-5f);
    }
    __syncthreads();
    float m = smean, r = srstd;
    out[(size_t)row * DD + t]       = __float2half_rn((v0 - m) * r * g[t]       + be[t]);
    out[(size_t)row * DD + t + 256] = __float2half_rn((v1 - m) * r * g[t + 256] + be[t + 256]);
}

// ---------------- top-16 + softmax + sparse A*V(fp16) -> fp16 ---------------
// Group-local logits (GRPB batches); real batch = bbase + local.
__global__ void __launch_bounds__(256) topk_kernel(
    const float* __restrict__ logits, const __half* __restrict__ v,
    __half* __restrict__ attn, int bbase)
{
    int w = (blockIdx.x * blockDim.x + threadIdx.x) >> 5;  // local row in group
    int lane = threadIdx.x & 31;
    int n = w & (NN - 1);
    int h = (w >> 9) & 7;
    int b = bbase + (w >> 12);

    const float* lrow = logits + (size_t)w * NN;
    float vals[16];
    #pragma unroll
    for (int t = 0; t < 16; t++) vals[t] = lrow[t * 32 + lane];

    unsigned mask = 0xFFFFu;
    float selv = 0.f;
    int   selm = 0;
    #pragma unroll
    for (int r = 0; r < 16; r++) {
        float bv = -INFINITY; int bs = 0;
        #pragma unroll
        for (int t = 0; t < 16; t++) {
            bool live = (mask >> t) & 1u;
            if (live && vals[t] > bv) { bv = vals[t]; bs = t; }
        }
        float rv = bv;
        int rm = bs * 32 + lane;
        #pragma unroll
        for (int off = 16; off; off >>= 1) {
            float ov = __shfl_xor_sync(0xFFFFFFFFu, rv, off);
            int   om = __shfl_xor_sync(0xFFFFFFFFu, rm, off);
            if (ov > rv || (ov == rv && om < rm)) { rv = ov; rm = om; }
        }
        if ((rm & 31) == lane) mask &= ~(1u << (rm >> 5));
        if (lane == r) { selv = rv; selm = rm; }
    }

    float maxv = __shfl_sync(0xFFFFFFFFu, selv, 0);
    float e = (lane < 16) ? expf(selv - maxv) : 0.f;
    float s = e;
    #pragma unroll
    for (int off = 16; off; off >>= 1) s += __shfl_xor_sync(0xFFFFFFFFu, s, off);
    float p = e / s;

    float o0 = 0.f, o1 = 0.f;
    const __half* vbase = v + ((size_t)b * NN) * DD + h * HD;
    #pragma unroll
    for (int l = 0; l < 16; l++) {
        float pl = __shfl_sync(0xFFFFFFFFu, p, l);
        int   ml = __shfl_sync(0xFFFFFFFFu, selm, l);
        const __half* vr = vbase + (size_t)ml * DD;
        o0 += pl * __half2float(vr[lane]);
        o1 += pl * __half2float(vr[lane + 32]);
    }
    size_t base = ((size_t)(b * NN + n)) * DD + h * HD;
    attn[base + lane]      = __float2half_rn(o0);
    attn[base + lane + 32] = __float2half_rn(o1);
}

// ---------------------------------------------------------------------------
extern "C" void kernel_launch(void* const* d_in, const int* in_sizes, int n_in,
                              void* d_out, int out_size)
{
    const float* x   = (const float*)d_in[0];
    const float* wq  = (const float*)d_in[1];
    const float* bq  = (const float*)d_in[2];
    const float* wk  = (const float*)d_in[3];
    const float* bk  = (const float*)d_in[4];
    const float* wv  = (const float*)d_in[5];
    const float* bv  = (const float*)d_in[6];
    const float* wo  = (const float*)d_in[7];
    const float* bo  = (const float*)d_in[8];
    const float* g1  = (const float*)d_in[9];
    const float* be1 = (const float*)d_in[10];
    const float* g2  = (const float*)d_in[11];
    const float* be2 = (const float*)d_in[12];
    const float* w1  = (const float*)d_in[13];
    const float* bf1 = (const float*)d_in[14];
    const float* w2  = (const float*)d_in[15];
    const float* bf2 = (const float*)d_in[16];
    const float* rel = (const float*)d_in[17];
    float* out = (float*)d_out;

    float *logits, *x1;
    __nv_bfloat16 *qh, *ql, *kh, *kl, *xnh, *xnl, *wqkvh, *wqkvl;
    __half *vf, *attnf, *wof, *xn2f, *fff, *w1f, *w2f;
    cudaGetSymbolAddress((void**)&logits, g_logits);
    cudaGetSymbolAddress((void**)&x1,     g_x1);
    cudaGetSymbolAddress((void**)&qh,     g_qb_h);
    cudaGetSymbolAddress((void**)&ql,     g_qb_l);
    cudaGetSymbolAddress((void**)&kh,     g_kb_h);
    cudaGetSymbolAddress((void**)&kl,     g_kb_l);
    cudaGetSymbolAddress((void**)&xnh,    g_xnb_h);
    cudaGetSymbolAddress((void**)&xnl,    g_xnb_l);
    cudaGetSymbolAddress((void**)&wqkvh,  g_wqkv_h);
    cudaGetSymbolAddress((void**)&wqkvl,  g_wqkv_l);
    cudaGetSymbolAddress((void**)&vf,     g_vf);
    cudaGetSymbolAddress((void**)&attnf,  g_attnf);
    cudaGetSymbolAddress((void**)&wof,    g_wof);
    cudaGetSymbolAddress((void**)&xn2f,   g_xn2f);
    cudaGetSymbolAddress((void**)&fff,    g_fff);
    cudaGetSymbolAddress((void**)&w1f,    g_w1f);
    cudaGetSymbolAddress((void**)&w2f,    g_w2f);

    const int SMEM_GEMM = 2 * BUFB;   // 81920
    const int SMEM_FP16 = 2 * BUF2;   // 40960
    cudaFuncSetAttribute(gemm_qkv,     cudaFuncAttributeMaxDynamicSharedMemorySize, SMEM_GEMM);
    cudaFuncSetAttribute(logits_mma,   cudaFuncAttributeMaxDynamicSharedMemorySize, SMEM_GEMM);
    cudaFuncSetAttribute(gemm_fp16<0>, cudaFuncAttributeMaxDynamicSharedMemorySize, SMEM_FP16);
    cudaFuncSetAttribute(gemm_fp16<1>, cudaFuncAttributeMaxDynamicSharedMemorySize, SMEM_FP16);

    dim3 gD(DD / 128, ROWS / 128);       // 4 x 64
    dim3 gQKV(3 * DD / 128, ROWS / 128); // 12 x 64
    dim3 gF(DFF / 128, ROWS / 128);      // 16 x 64

    // 1. all weight converts in one launch
    prep_weights<<<dim3(16, 16, 12), 256>>>(wq, wk, wv, wo, w1, w2,
                                            wqkvh, wqkvl, wof, w1f, w2f);
    // 2. LN1 -> bf16 hi/lo
    ln_kernel<<<ROWS, 256>>>(x, g1, be1, xnh, xnl);
    // 3. fused QKV projection (Q,K bf16x3; V single -> fp16)
    gemm_qkv<<<gQKV, 256, SMEM_GEMM>>>(xnh, xnl, wqkvh, wqkvl,
                                       bq, bk, bv, qh, ql, kh, kl, vf);
    // 4+5. logits + topk, batch-grouped so logits stays L2-resident
    for (int g = 0; g < BB / GRPB; g++) {
        logits_mma<<<dim3(NN / 128, NN / 128, GRPB * HH), 256, SMEM_GEMM>>>(
            qh, ql, kh, kl, rel, logits, g * GRPB);
        topk_kernel<<<(GRPB * HH * NN * 32) / 256, 256>>>(logits, vf, attnf, g * GRPB);
    }
    // 6. output projection + residual (fp16 x1)
    gemm_fp16<1><<<gD, 256, SMEM_FP16>>>(attnf, wof, bo, x, x1, DD, DD);
    // 7. LN2 -> fp16
    ln_fp16<<<ROWS, 256>>>(x1, g2, be2, xn2f);
    // 8. FFN up + exact GELU (fp16 x1) -> fp16
    gemm_fp16<0><<<gF, 256, SMEM_FP16>>>(xn2f, w1f, bf1, nullptr, fff, DFF, DD);
    // 9. FFN down + residual (fp16 x1) -> output
    gemm_fp16<1><<<gD, 256, SMEM_FP16>>>(fff, w2f, bf2, x1, out, DD, DFF);
}